// round 6
// baseline (speedup 1.0000x reference)
#include <cuda_runtime.h>
#include <cuda_fp16.h>
#include <cstdint>

#define TB   512
#define TM1  127
#define ENCD 256
#define GB   4
#define NCTA (TB / GB)   // 128
#define NCA  23          // W1h chunks cached in smem (of 128)
#define NCB  32          // Whh chunks cached in smem (of 128)

typedef unsigned long long ull;

// ---------------- scratch (static device globals) ---------------------------
static __device__ __half g_EH[TB * TM1 * ENCD];    // E[b,t,k] fp16  (~33 MB)
static __device__ __half g_encH[TB * TM1 * ENCD];  // enc fp16       (~33 MB)
static __device__ uint2  g_W1h[128 * 256];         // (jb,k): 4 fp16 of W1hc[k][4jb..]
static __device__ uint4  g_WhhH[128 * 256];        // (j2,k): half2 (IF_j0,GO_j0,IF_j1,GO_j1)
static __device__ float  g_W1eT[256 * 256];        // [j][k]: W_attn1[k][512+j]
static __device__ float4 g_bih4[256];              // b_ih+b_hh per gate
static __device__ float4 g_wih4[256];              // W_ih per gate

// ---------------- dynamic smem layout ---------------------------------------
struct SmemT {
    uint4    sWh[NCB * 256];     // 131072
    uint2    sW1[NCA * 256];     // 47104
    float4   sbufA[1024];        // 16384 : A partials (float view) / D exchange
    float4   sbufC[512];         // 8192  : C2 partials
    float    shc[GB][512];       // 8192  : h | c (f32)
    float    sphc[GB][256];      // 4096
    float    sctx[GB][256];      // 4096
    float    sattn[GB][128];     // 2048
    unsigned shD[GB][256];       // 4096  : splat half2(h_j,h_j)
    float    w2s[256];           // 1024
    float    wfcs[256];          // 1024
    float    syh[GB][128];       // 2048
    float    spart[8];
    float    sred[32];
};

// ---------------- math helpers ----------------------------------------------
__device__ __forceinline__ float tanh_fast(float x) {
    float y; asm("tanh.approx.f32 %0, %1;" : "=f"(y) : "f"(x)); return y;
}
__device__ __forceinline__ float sigm(float x) { return 1.f / (1.f + __expf(-x)); }
__device__ __forceinline__ float tanh_acc(float x) {
    float e = __expf(2.f * x); return 1.f - 2.f / (e + 1.f);
}
__device__ __forceinline__ ull pk2(float x, float y) {
    ull r; asm("mov.b64 %0, {%1,%2};" : "=l"(r) : "f"(x), "f"(y)); return r;
}
__device__ __forceinline__ void fma2(ull& d, ull a, ull b) {
    asm("fma.rn.f32x2 %0, %1, %2, %0;" : "+l"(d) : "l"(a), "l"(b));
}
__device__ __forceinline__ float2 up2(ull v) {
    float2 f; asm("mov.b64 {%0,%1}, %2;" : "=f"(f.x), "=f"(f.y) : "l"(v)); return f;
}
__device__ __forceinline__ float2 h2f(unsigned u) {
    return __half22float2(*(__half2*)&u);
}
__device__ __forceinline__ __half2 uh2(unsigned u) { return *(__half2*)&u; }

// ---------------- prep: packing / fp16 conversion ---------------------------
__global__ void prep_kernel(const float* __restrict__ W1, const float* __restrict__ Whh,
                            const float* __restrict__ bih, const float* __restrict__ bhh,
                            const float* __restrict__ Wih, const float* __restrict__ enc) {
    const int tid = blockIdx.x * blockDim.x + threadIdx.x;
    const int stride = gridDim.x * blockDim.x;
    for (int i = tid; i < 128 * 256; i += stride) {
        int jb = i >> 8, k = i & 255;
        const float* p = W1 + k * 768 + jb * 4;
        __half2 a = __floats2half2_rn(p[0], p[1]);
        __half2 b = __floats2half2_rn(p[2], p[3]);
        uint2 u; u.x = *(unsigned*)&a; u.y = *(unsigned*)&b;
        g_W1h[i] = u;
    }
    for (int i = tid; i < 256 * 256; i += stride) {
        int j = i >> 8, k = i & 255;
        g_W1eT[i] = W1[k * 768 + 512 + j];
    }
    for (int i = tid; i < 128 * 256; i += stride) {
        int j2 = i >> 8, k = i & 255;
        int j0 = j2 * 2, j1 = j0 + 1;
        __half2 a = __floats2half2_rn(Whh[k * 256 + j0],         Whh[(k + 256) * 256 + j0]);
        __half2 b = __floats2half2_rn(Whh[(k + 512) * 256 + j0], Whh[(k + 768) * 256 + j0]);
        __half2 c = __floats2half2_rn(Whh[k * 256 + j1],         Whh[(k + 256) * 256 + j1]);
        __half2 d = __floats2half2_rn(Whh[(k + 512) * 256 + j1], Whh[(k + 768) * 256 + j1]);
        uint4 u; u.x = *(unsigned*)&a; u.y = *(unsigned*)&b;
        u.z = *(unsigned*)&c; u.w = *(unsigned*)&d;
        g_WhhH[i] = u;
    }
    for (int i = tid; i < 256; i += stride) {
        g_bih4[i] = make_float4(bih[i] + bhh[i], bih[i + 256] + bhh[i + 256],
                                bih[i + 512] + bhh[i + 512], bih[i + 768] + bhh[i + 768]);
        g_wih4[i] = make_float4(Wih[i], Wih[i + 256], Wih[i + 512], Wih[i + 768]);
    }
    const int n = TB * TM1 * ENCD;
    for (int i = tid; i < n; i += stride) g_encH[i] = __float2half(enc[i]);
}

// ---------------- E = enc @ W_e^T + b_attn1 (fp16 out) ----------------------
__global__ __launch_bounds__(256) void e_gemm(const float* __restrict__ A,
                                              const float* __restrict__ bias) {
    __shared__ float As[16][64];
    __shared__ float Bs[16][64];
    const int tid = threadIdx.x;
    const int row0 = blockIdx.x * 64;
    const int col0 = blockIdx.y * 64;
    const int tx = tid & 15, ty = tid >> 4;
    float acc[4][4] = {};
    for (int k0 = 0; k0 < 256; k0 += 16) {
        #pragma unroll
        for (int i = tid; i < 1024; i += 256) {
            int m = i >> 4, kk = i & 15;
            As[kk][m] = A[(size_t)(row0 + m) * 256 + k0 + kk];
        }
        {
            int kk = tid >> 4, n4 = tid & 15;
            ((float4*)&Bs[kk][0])[n4] =
                ((const float4*)&g_W1eT[(k0 + kk) * 256 + col0])[n4];
        }
        __syncthreads();
        #pragma unroll
        for (int kk = 0; kk < 16; kk++) {
            float4 av = ((const float4*)&As[kk][0])[ty];
            float4 bv = ((const float4*)&Bs[kk][0])[tx];
            acc[0][0] += av.x * bv.x; acc[0][1] += av.x * bv.y; acc[0][2] += av.x * bv.z; acc[0][3] += av.x * bv.w;
            acc[1][0] += av.y * bv.x; acc[1][1] += av.y * bv.y; acc[1][2] += av.y * bv.z; acc[1][3] += av.y * bv.w;
            acc[2][0] += av.z * bv.x; acc[2][1] += av.z * bv.y; acc[2][2] += av.z * bv.z; acc[2][3] += av.z * bv.w;
            acc[3][0] += av.w * bv.x; acc[3][1] += av.w * bv.y; acc[3][2] += av.w * bv.z; acc[3][3] += av.w * bv.w;
        }
        __syncthreads();
    }
    float4 bv = ((const float4*)(bias + col0))[tx];
    #pragma unroll
    for (int i = 0; i < 4; i++) {
        int row = row0 + ty * 4 + i;
        __half2 h01 = __floats2half2_rn(acc[i][0] + bv.x, acc[i][1] + bv.y);
        __half2 h23 = __floats2half2_rn(acc[i][2] + bv.z, acc[i][3] + bv.w);
        uint2 u; u.x = *(unsigned*)&h01; u.y = *(unsigned*)&h23;
        ((uint2*)(g_EH + (size_t)row * 256 + col0))[tx] = u;
    }
}

// ---------------- persistent decoder: 1024 threads, A-all then B||D ---------
__global__ __launch_bounds__(1024, 1) void decoder_kernel(
    const float* __restrict__ yhist, const float* __restrict__ w2,
    const float* __restrict__ Wfc, const float* __restrict__ bfc,
    const float* __restrict__ Wfcf, const float* __restrict__ bfcf,
    float* __restrict__ out) {
    extern __shared__ char smem_raw[];
    SmemT& s = *(SmemT*)smem_raw;

    const int tid = threadIdx.x;
    const int lane = tid & 31, warp = tid >> 5;
    const int bs = blockIdx.x * GB;
    const int k = tid & 255;

    // ---- init --------------------------------------------------------------
    for (int i = tid; i < NCA * 256; i += 1024) s.sW1[i] = g_W1h[i];
    for (int i = tid; i < NCB * 256; i += 1024) s.sWh[i] = g_WhhH[i];
    if (tid < 512) {
        int g = tid >> 7, t = tid & 127;
        if (t < TM1) s.syh[g][t] = yhist[(bs + g) * TM1 + t];
    }
    if (tid < 256) {
        s.w2s[tid] = w2[tid]; s.wfcs[tid] = Wfc[tid];
        #pragma unroll
        for (int g = 0; g < GB; g++) {
            s.shc[g][tid] = 0.f; s.shc[g][256 + tid] = 0.f; s.shD[g][tid] = 0u;
        }
    }
    const float wfc_y = Wfc[256];
    const float bfc_v = bfc[0];
    float4 b4 = make_float4(0, 0, 0, 0), wi4 = b4;
    if (tid >= 512 && tid < 768) { b4 = g_bih4[k]; wi4 = g_wih4[k]; }
    __syncthreads();

    for (int step = 0; step < TM1; step++) {
        // ==== Phase A (all 1024): phc partials, 4-way jb split ===============
        {
            const int q4 = tid >> 8;
            ull a2[GB] = {0ull, 0ull, 0ull, 0ull};
            const int iC = (NCA - q4 + 3) >> 2;
            #pragma unroll 4
            for (int i = 0; i < iC; i++) {
                int jb = q4 + 4 * i;
                uint2 w = s.sW1[(jb << 8) + k];
                float2 w01 = h2f(w.x), w23 = h2f(w.y);
                ull W01 = pk2(w01.x, w01.y), W23 = pk2(w23.x, w23.y);
                #pragma unroll
                for (int g = 0; g < GB; g++) {
                    float4 x = ((const float4*)s.shc[g])[jb];
                    fma2(a2[g], W01, pk2(x.x, x.y));
                    fma2(a2[g], W23, pk2(x.z, x.w));
                }
            }
            #pragma unroll 4
            for (int i = iC; i < 32; i++) {
                int jb = q4 + 4 * i;
                uint2 w = g_W1h[(jb << 8) + k];
                float2 w01 = h2f(w.x), w23 = h2f(w.y);
                ull W01 = pk2(w01.x, w01.y), W23 = pk2(w23.x, w23.y);
                #pragma unroll
                for (int g = 0; g < GB; g++) {
                    float4 x = ((const float4*)s.shc[g])[jb];
                    fma2(a2[g], W01, pk2(x.x, x.y));
                    fma2(a2[g], W23, pk2(x.z, x.w));
                }
            }
            #pragma unroll
            for (int g = 0; g < GB; g++) {
                float2 f = up2(a2[g]);
                ((float*)s.sbufA)[(q4 << 10) + (g << 8) + k] = f.x + f.y;
            }
        }
        __syncthreads();
        if (tid < 256) {   // A reduce -> sphc
            const float* pb = (const float*)s.sbufA;
            #pragma unroll
            for (int g = 0; g < GB; g++) {
                int o = (g << 8) + tid;
                s.sphc[g][tid] = pb[o] + pb[1024 + o] + pb[2048 + o] + pb[3072 + o];
            }
        }
        __syncthreads();

        float2 fIF[GB], fGO[GB];   // D accumulators (live in lstm-group regs)
        if (tid < 512) {
            // ==== Phase B (warps 0-15): scores ===============================
            for (int t = warp; t < TM1; t += 16) {
                const uint2* Ev = (const uint2*)(g_EH + ((size_t)bs * TM1 + t) * 256);
                float sc[GB] = {0.f, 0.f, 0.f, 0.f};
                #pragma unroll
                for (int it = 0; it < 2; it++) {
                    int q = lane + (it << 5);
                    float4 wv = ((const float4*)s.w2s)[q];
                    #pragma unroll
                    for (int g = 0; g < GB; g++) {
                        uint2 e = Ev[g * (TM1 * 64) + q];
                        float2 e01 = h2f(e.x), e23 = h2f(e.y);
                        float4 p = ((const float4*)s.sphc[g])[q];
                        sc[g] += wv.x * tanh_fast(p.x + e01.x) + wv.y * tanh_fast(p.y + e01.y)
                               + wv.z * tanh_fast(p.z + e23.x) + wv.w * tanh_fast(p.w + e23.y);
                    }
                }
                #pragma unroll
                for (int o = 16; o; o >>= 1) {
                    #pragma unroll
                    for (int g = 0; g < GB; g++)
                        sc[g] += __shfl_xor_sync(0xffffffffu, sc[g], o);
                }
                if (lane == 0) {
                    #pragma unroll
                    for (int g = 0; g < GB; g++) s.sattn[g][t] = sc[g];
                }
            }
            asm volatile("bar.sync 1, 512;" ::: "memory");
            // ==== Phase C1 (warps 0-3): softmax + write attn rows ============
            if (warp < GB) {
                const int g = warp;
                float m = -1e30f;
                for (int t = lane; t < TM1; t += 32) m = fmaxf(m, s.sattn[g][t]);
                #pragma unroll
                for (int o = 16; o; o >>= 1) m = fmaxf(m, __shfl_xor_sync(0xffffffffu, m, o));
                float sum = 0.f;
                for (int t = lane; t < TM1; t += 32) {
                    float e = __expf(s.sattn[g][t] - m); s.sattn[g][t] = e; sum += e;
                }
                #pragma unroll
                for (int o = 16; o; o >>= 1) sum += __shfl_xor_sync(0xffffffffu, sum, o);
                const float inv = 1.f / sum;
                float* wrow = out + TB + ((size_t)(bs + g) * TM1 + step) * TM1;
                for (int t = lane; t < TM1; t += 32) {
                    float a = s.sattn[g][t] * inv; s.sattn[g][t] = a; wrow[t] = a;
                }
            }
        } else {
            // ==== Phase D (warps 16-31): gates = Whh @ h, HFMA2, j-split =====
            const int jh = (tid >> 8) & 1;   // 0: even j2, 1: odd j2
            __half2 hIF[GB], hGO[GB];
            #pragma unroll
            for (int g = 0; g < GB; g++) {
                hIF[g] = __float2half2_rn(0.f); hGO[g] = __float2half2_rn(0.f);
                fIF[g] = make_float2(0.f, 0.f); fGO[g] = make_float2(0.f, 0.f);
            }
            int i = 0;
            #pragma unroll
            for (int ch = 0; ch < 2; ch++) {          // cached chunks (16 i)
                #pragma unroll
                for (int u = 0; u < 8; u++, i++) {
                    int j2 = jh + 2 * i;
                    uint4 w = s.sWh[(j2 << 8) + k];
                    #pragma unroll
                    for (int g = 0; g < GB; g++) {
                        uint2 H2 = *(const uint2*)&s.shD[g][2 * j2];
                        __half2 H0 = uh2(H2.x), H1 = uh2(H2.y);
                        hIF[g] = __hfma2(uh2(w.x), H0, hIF[g]);
                        hGO[g] = __hfma2(uh2(w.y), H0, hGO[g]);
                        hIF[g] = __hfma2(uh2(w.z), H1, hIF[g]);
                        hGO[g] = __hfma2(uh2(w.w), H1, hGO[g]);
                    }
                }
                #pragma unroll
                for (int g = 0; g < GB; g++) {
                    float2 a = __half22float2(hIF[g]), b = __half22float2(hGO[g]);
                    fIF[g].x += a.x; fIF[g].y += a.y; fGO[g].x += b.x; fGO[g].y += b.y;
                    hIF[g] = __float2half2_rn(0.f); hGO[g] = __float2half2_rn(0.f);
                }
            }
            for (int ch = 0; ch < 6; ch++) {          // streamed chunks (48 i)
                #pragma unroll
                for (int u = 0; u < 8; u++, i++) {
                    int j2 = jh + 2 * i;
                    uint4 w = g_WhhH[(j2 << 8) + k];
                    #pragma unroll
                    for (int g = 0; g < GB; g++) {
                        uint2 H2 = *(const uint2*)&s.shD[g][2 * j2];
                        __half2 H0 = uh2(H2.x), H1 = uh2(H2.y);
                        hIF[g] = __hfma2(uh2(w.x), H0, hIF[g]);
                        hGO[g] = __hfma2(uh2(w.y), H0, hGO[g]);
                        hIF[g] = __hfma2(uh2(w.z), H1, hIF[g]);
                        hGO[g] = __hfma2(uh2(w.w), H1, hGO[g]);
                    }
                }
                #pragma unroll
                for (int g = 0; g < GB; g++) {
                    float2 a = __half22float2(hIF[g]), b = __half22float2(hGO[g]);
                    fIF[g].x += a.x; fIF[g].y += a.y; fGO[g].x += b.x; fGO[g].y += b.y;
                    hIF[g] = __float2half2_rn(0.f); hGO[g] = __float2half2_rn(0.f);
                }
            }
            if (jh == 1) {   // exchange odd-half partials
                #pragma unroll
                for (int g = 0; g < GB; g++)
                    s.sbufA[(g << 8) + k] =
                        make_float4(fIF[g].x, fIF[g].y, fGO[g].x, fGO[g].y);
            }
        }
        __syncthreads();   // join: sattn ready, D partials exchanged
        // ==== Phase C2 (tid<512): context partials, 2-way t split ============
        if (tid < 512) {
            const int g = tid >> 7, q = tid & 63, th = (tid >> 6) & 1;
            const uint2* ev = (const uint2*)(g_encH + ((size_t)(bs + g) * TM1) * 256) + q;
            ull acc01 = 0ull, acc23 = 0ull;
            const int t0 = th << 6, t1 = th ? TM1 : 64;
            #pragma unroll 4
            for (int t = t0; t < t1; t++) {
                float a = s.sattn[g][t];
                uint2 v = ev[(size_t)t << 6];
                float2 v01 = h2f(v.x), v23 = h2f(v.y);
                ull A = pk2(a, a);
                fma2(acc01, A, pk2(v01.x, v01.y));
                fma2(acc23, A, pk2(v23.x, v23.y));
            }
            float2 a01 = up2(acc01), a23 = up2(acc23);
            s.sbufC[((g << 1) | th) << 6 | q] = make_float4(a01.x, a01.y, a23.x, a23.y);
        } else if (tid < 768) {
            // fold in odd-half D partials
            #pragma unroll
            for (int g = 0; g < GB; g++) {
                float4 p = s.sbufA[(g << 8) + k];
                fIF[g].x += p.x; fIF[g].y += p.y; fGO[g].x += p.z; fGO[g].y += p.w;
            }
        }
        __syncthreads();
        // ==== C2 reduce + y partials (warps 0-7) =============================
        if (warp < 8) {
            const int g = warp >> 1, hf = warp & 1;
            const int idx = (hf << 5) + lane;          // 0..63
            float4 o = s.sbufC[(g << 7) | idx];
            float4 p = s.sbufC[(g << 7) | 64 | idx];
            float4 c4 = make_float4(o.x + p.x, o.y + p.y, o.z + p.z, o.w + p.w);
            ((float4*)s.sctx[g])[idx] = c4;
            float4 wv = ((const float4*)s.wfcs)[idx];
            float v = wv.x * c4.x + wv.y * c4.y + wv.z * c4.z + wv.w * c4.w;
            #pragma unroll
            for (int o2 = 16; o2; o2 >>= 1) v += __shfl_xor_sync(0xffffffffu, v, o2);
            if (lane == 0) s.spart[(g << 1) + hf] = v;
        }
        __syncthreads();
        // ==== combine + state update (tid 512-767) ===========================
        if (tid >= 512 && tid < 768) {
            #pragma unroll
            for (int g = 0; g < GB; g++) {
                float y = bfc_v + wfc_y * s.syh[g][step] + s.spart[2 * g] + s.spart[2 * g + 1];
                float gi = fIF[g].x + b4.x + wi4.x * y;
                float gf = fIF[g].y + b4.y + wi4.y * y;
                float gg = fGO[g].x + b4.z + wi4.z * y;
                float go = fGO[g].y + b4.w + wi4.w * y;
                float cold = s.shc[g][256 + k];
                float cn = sigm(gf) * cold + sigm(gi) * tanh_acc(gg);
                float hn = sigm(go) * tanh_acc(cn);
                s.shc[g][256 + k] = cn;
                s.shc[g][k] = hn;
                __half2 hs = __float2half2_rn(hn);
                s.shD[g][k] = *(unsigned*)&hs;
            }
        }
        __syncthreads();   // end of step
    }
    // ---- final: out[b] = b_fcf + Wfcf . [h ; context] -----------------------
    #pragma unroll
    for (int g = 0; g < GB; g++) {
        float v = (tid < 256)
                    ? (Wfcf[k] * s.shc[g][k] + Wfcf[256 + k] * s.sctx[g][k]) : 0.f;
        #pragma unroll
        for (int o = 16; o; o >>= 1) v += __shfl_down_sync(0xffffffffu, v, o);
        if (lane == 0) s.sred[warp] = v;
        __syncthreads();
        if (warp == 0) {
            float r = s.sred[lane];
            #pragma unroll
            for (int o = 16; o; o >>= 1) r += __shfl_down_sync(0xffffffffu, r, o);
            if (lane == 0) out[bs + g] = bfcf[0] + r;
        }
        __syncthreads();
    }
}

// ---------------- launch -----------------------------------------------------
extern "C" void kernel_launch(void* const* d_in, const int* in_sizes, int n_in,
                              void* d_out, int out_size) {
    const float* enc  = (const float*)d_in[0];
    const float* yh   = (const float*)d_in[1];
    const float* W1   = (const float*)d_in[2];
    const float* b1   = (const float*)d_in[3];
    const float* W2   = (const float*)d_in[4];
    // d_in[5] = b_attn2: softmax-invariant, unused
    const float* Wih  = (const float*)d_in[6];
    const float* Whh  = (const float*)d_in[7];
    const float* bih  = (const float*)d_in[8];
    const float* bhh  = (const float*)d_in[9];
    const float* Wfc  = (const float*)d_in[10];
    const float* bfc  = (const float*)d_in[11];
    const float* Wfcf = (const float*)d_in[12];
    const float* bfcf = (const float*)d_in[13];
    float* out = (float*)d_out;

    static bool attr_done = false;
    if (!attr_done) {
        cudaFuncSetAttribute(decoder_kernel,
                             cudaFuncAttributeMaxDynamicSharedMemorySize, sizeof(SmemT));
        attr_done = true;
    }
    prep_kernel<<<256, 256>>>(W1, Whh, bih, bhh, Wih, enc);
    e_gemm<<<dim3(1016, 4), 256>>>(enc, b1);
    decoder_kernel<<<NCTA, 1024, sizeof(SmemT)>>>(yh, W2, Wfc, bfc, Wfcf, bfcf, out);
}

// round 12
// speedup vs baseline: 1.1598x; 1.1598x over previous
#include <cuda_runtime.h>
#include <cuda_fp16.h>
#include <cstdint>

#define TB   512
#define TM1  127
#define ENCD 256
#define GB   4
#define NCTA (TB / GB)   // 128
#define NCA  23          // W1h chunks cached in smem (of 128)
#define NCB  32          // Whh chunks cached in smem (of 128)

typedef unsigned long long ull;

// ---------------- scratch (static device globals) ---------------------------
static __device__ __half g_EH[TB * TM1 * ENCD];    // E[b,t,k] fp16  (~33 MB)
static __device__ __half g_encH[TB * TM1 * ENCD];  // enc fp16       (~33 MB)
static __device__ uint2  g_W1h[128 * 256];         // (jb,k): half2(w_j0,w_j1), half2(w_j2,w_j3)
static __device__ uint4  g_WhhH[128 * 256];        // (j2,k): half2 (IF_j0, GO_j0, IF_j1, GO_j1)
static __device__ float  g_W1eT[256 * 256];        // [j][k]: W_attn1[k][512+j]
static __device__ float4 g_bih4[256];              // b_ih+b_hh per gate
static __device__ float4 g_wih4[256];              // W_ih per gate

// ---------------- dynamic smem layout ---------------------------------------
struct SmemT {
    uint4    sWh[NCB * 256];       // 131072 : Whh cache
    uint2    sW1[NCA * 256];       // 47104  : W1h cache
    uint2    shD2[128][4];         // 4096   : [j2][g] = (splat h_{2j2}, splat h_{2j2+1})
    unsigned sHA[128][8];          // 4096   : [jb][g*2+slot]; jb<64: h pairs, jb>=64: c pairs
    unsigned sphcH[GB][128];       // 2048   : half2 (phc_2m, phc_2m+1)
    float    sbufA[4][GB][256];    // 16384  : A partials / D exchange (float4 view)
    float4   sbufC[512];           // 8192   : C2 partials
    float    shc[GB][512];         // 8192   : h | c (f32)
    float    sctx[GB][256];        // 4096
    float    sattn[GB][128];       // 2048
    float    w2s[256];             // 1024
    float    wfcs[256];            // 1024
    float    syh[GB][128];         // 2048
    float    spart[8];
    float    sred[32];
};

// ---------------- math helpers ----------------------------------------------
__device__ __forceinline__ float sigm(float x) { return 1.f / (1.f + __expf(-x)); }
__device__ __forceinline__ float tanh_acc(float x) {
    float e = __expf(2.f * x); return 1.f - 2.f / (e + 1.f);
}
__device__ __forceinline__ ull pk2(float x, float y) {
    ull r; asm("mov.b64 %0, {%1,%2};" : "=l"(r) : "f"(x), "f"(y)); return r;
}
__device__ __forceinline__ void fma2(ull& d, ull a, ull b) {
    asm("fma.rn.f32x2 %0, %1, %2, %0;" : "+l"(d) : "l"(a), "l"(b));
}
__device__ __forceinline__ float2 up2(ull v) {
    float2 f; asm("mov.b64 {%0,%1}, %2;" : "=f"(f.x), "=f"(f.y) : "l"(v)); return f;
}
__device__ __forceinline__ __half2 uh2(unsigned u) { return *(__half2*)&u; }
__device__ __forceinline__ unsigned h2u(__half2 h) { return *(unsigned*)&h; }
__device__ __forceinline__ unsigned tanh2u(unsigned x) {
    unsigned y; asm("tanh.approx.f16x2 %0, %1;" : "=r"(y) : "r"(x)); return y;
}

// ---------------- prep: packing / fp16 conversion ---------------------------
__global__ void prep_kernel(const float* __restrict__ W1, const float* __restrict__ Whh,
                            const float* __restrict__ bih, const float* __restrict__ bhh,
                            const float* __restrict__ Wih, const float* __restrict__ enc) {
    const int tid = blockIdx.x * blockDim.x + threadIdx.x;
    const int stride = gridDim.x * blockDim.x;
    for (int i = tid; i < 128 * 256; i += stride) {
        int jb = i >> 8, k = i & 255;
        const float* p = W1 + k * 768 + jb * 4;
        __half2 a = __floats2half2_rn(p[0], p[1]);
        __half2 b = __floats2half2_rn(p[2], p[3]);
        uint2 u; u.x = h2u(a); u.y = h2u(b);
        g_W1h[i] = u;
    }
    for (int i = tid; i < 256 * 256; i += stride) {
        int j = i >> 8, k = i & 255;
        g_W1eT[i] = W1[k * 768 + 512 + j];
    }
    for (int i = tid; i < 128 * 256; i += stride) {
        int j2 = i >> 8, k = i & 255;
        int j0 = j2 * 2, j1 = j0 + 1;
        __half2 a = __floats2half2_rn(Whh[k * 256 + j0],         Whh[(k + 256) * 256 + j0]);
        __half2 b = __floats2half2_rn(Whh[(k + 512) * 256 + j0], Whh[(k + 768) * 256 + j0]);
        __half2 c = __floats2half2_rn(Whh[k * 256 + j1],         Whh[(k + 256) * 256 + j1]);
        __half2 d = __floats2half2_rn(Whh[(k + 512) * 256 + j1], Whh[(k + 768) * 256 + j1]);
        uint4 u; u.x = h2u(a); u.y = h2u(b); u.z = h2u(c); u.w = h2u(d);
        g_WhhH[i] = u;
    }
    for (int i = tid; i < 256; i += stride) {
        g_bih4[i] = make_float4(bih[i] + bhh[i], bih[i + 256] + bhh[i + 256],
                                bih[i + 512] + bhh[i + 512], bih[i + 768] + bhh[i + 768]);
        g_wih4[i] = make_float4(Wih[i], Wih[i + 256], Wih[i + 512], Wih[i + 768]);
    }
    const int n = TB * TM1 * ENCD;
    for (int i = tid; i < n; i += stride) g_encH[i] = __float2half(enc[i]);
}

// ---------------- E = enc @ W_e^T + b_attn1 (fp16 out) ----------------------
__global__ __launch_bounds__(256) void e_gemm(const float* __restrict__ A,
                                              const float* __restrict__ bias) {
    __shared__ float As[16][64];
    __shared__ float Bs[16][64];
    const int tid = threadIdx.x;
    const int row0 = blockIdx.x * 64;
    const int col0 = blockIdx.y * 64;
    const int tx = tid & 15, ty = tid >> 4;
    float acc[4][4] = {};
    for (int k0 = 0; k0 < 256; k0 += 16) {
        #pragma unroll
        for (int i = tid; i < 1024; i += 256) {
            int m = i >> 4, kk = i & 15;
            As[kk][m] = A[(size_t)(row0 + m) * 256 + k0 + kk];
        }
        {
            int kk = tid >> 4, n4 = tid & 15;
            ((float4*)&Bs[kk][0])[n4] =
                ((const float4*)&g_W1eT[(k0 + kk) * 256 + col0])[n4];
        }
        __syncthreads();
        #pragma unroll
        for (int kk = 0; kk < 16; kk++) {
            float4 av = ((const float4*)&As[kk][0])[ty];
            float4 bv = ((const float4*)&Bs[kk][0])[tx];
            acc[0][0] += av.x * bv.x; acc[0][1] += av.x * bv.y; acc[0][2] += av.x * bv.z; acc[0][3] += av.x * bv.w;
            acc[1][0] += av.y * bv.x; acc[1][1] += av.y * bv.y; acc[1][2] += av.y * bv.z; acc[1][3] += av.y * bv.w;
            acc[2][0] += av.z * bv.x; acc[2][1] += av.z * bv.y; acc[2][2] += av.z * bv.z; acc[2][3] += av.z * bv.w;
            acc[3][0] += av.w * bv.x; acc[3][1] += av.w * bv.y; acc[3][2] += av.w * bv.z; acc[3][3] += av.w * bv.w;
        }
        __syncthreads();
    }
    float4 bv = ((const float4*)(bias + col0))[tx];
    #pragma unroll
    for (int i = 0; i < 4; i++) {
        int row = row0 + ty * 4 + i;
        __half2 h01 = __floats2half2_rn(acc[i][0] + bv.x, acc[i][1] + bv.y);
        __half2 h23 = __floats2half2_rn(acc[i][2] + bv.z, acc[i][3] + bv.w);
        uint2 u; u.x = h2u(h01); u.y = h2u(h23);
        ((uint2*)(g_EH + (size_t)row * 256 + col0))[tx] = u;
    }
}

// ---------------- persistent decoder: 1024 threads ---------------------------
__global__ __launch_bounds__(1024, 1) void decoder_kernel(
    const float* __restrict__ yhist, const float* __restrict__ w2,
    const float* __restrict__ Wfc, const float* __restrict__ bfc,
    const float* __restrict__ Wfcf, const float* __restrict__ bfcf,
    float* __restrict__ out) {
    extern __shared__ char smem_raw[];
    SmemT& s = *(SmemT*)smem_raw;

    const int tid = threadIdx.x;
    const int lane = tid & 31, warp = tid >> 5;
    const int bs = blockIdx.x * GB;
    const int k = tid & 255;

    // ---- init --------------------------------------------------------------
    for (int i = tid; i < NCA * 256; i += 1024) s.sW1[i] = g_W1h[i];
    for (int i = tid; i < NCB * 256; i += 1024) s.sWh[i] = g_WhhH[i];
    ((unsigned*)s.sHA)[tid] = 0u;   // 1024 entries: h and c pair tables
    if (tid < 512) {
        int g = tid >> 7, t = tid & 127;
        if (t < TM1) s.syh[g][t] = yhist[(bs + g) * TM1 + t];
        ((uint2*)s.shD2)[tid] = make_uint2(0u, 0u);
        ((unsigned*)s.sphcH)[tid] = 0u;
    }
    if (tid < 256) {
        s.w2s[tid] = w2[tid]; s.wfcs[tid] = Wfc[tid];
        #pragma unroll
        for (int g = 0; g < GB; g++) { s.shc[g][tid] = 0.f; s.shc[g][256 + tid] = 0.f; }
    }
    const float wfc_y = Wfc[256];
    const float bfc_v = bfc[0];
    __syncthreads();

    for (int step = 0; step < TM1; step++) {
        // ==== Phase A (all 1024): phc partials, HFMA2, 4-way jb split ========
        // j covers [h;c]: sHA[jb<64]=h pairs, sHA[jb>=64]=c pairs
        {
            const int q4 = tid >> 8;
            __half2 acc[GB];
            float facc[GB];
            #pragma unroll
            for (int g = 0; g < GB; g++) { acc[g] = __float2half2_rn(0.f); facc[g] = 0.f; }
            const int iC = (NCA > q4) ? ((NCA - q4 + 3) >> 2) : 0;
            int i = 0;
            #pragma unroll 4
            for (; i < iC; i++) {
                const int jb = q4 + 4 * i;
                uint2 w = s.sW1[(jb << 8) + k];
                #pragma unroll
                for (int gg = 0; gg < GB; gg += 2) {
                    uint4 H = *(const uint4*)&s.sHA[jb][gg * 2];
                    acc[gg]     = __hfma2(uh2(w.x), uh2(H.x), acc[gg]);
                    acc[gg]     = __hfma2(uh2(w.y), uh2(H.y), acc[gg]);
                    acc[gg + 1] = __hfma2(uh2(w.x), uh2(H.z), acc[gg + 1]);
                    acc[gg + 1] = __hfma2(uh2(w.y), uh2(H.w), acc[gg + 1]);
                }
                if ((i & 3) == 3) {
                    #pragma unroll
                    for (int g = 0; g < GB; g++) {
                        float2 f = __half22float2(acc[g]);
                        facc[g] += f.x + f.y; acc[g] = __float2half2_rn(0.f);
                    }
                }
            }
            #pragma unroll 4
            for (; i < 32; i++) {
                const int jb = q4 + 4 * i;
                uint2 w = g_W1h[(jb << 8) + k];
                #pragma unroll
                for (int gg = 0; gg < GB; gg += 2) {
                    uint4 H = *(const uint4*)&s.sHA[jb][gg * 2];
                    acc[gg]     = __hfma2(uh2(w.x), uh2(H.x), acc[gg]);
                    acc[gg]     = __hfma2(uh2(w.y), uh2(H.y), acc[gg]);
                    acc[gg + 1] = __hfma2(uh2(w.x), uh2(H.z), acc[gg + 1]);
                    acc[gg + 1] = __hfma2(uh2(w.y), uh2(H.w), acc[gg + 1]);
                }
                if ((i & 3) == 3) {
                    #pragma unroll
                    for (int g = 0; g < GB; g++) {
                        float2 f = __half22float2(acc[g]);
                        facc[g] += f.x + f.y; acc[g] = __float2half2_rn(0.f);
                    }
                }
            }
            #pragma unroll
            for (int g = 0; g < GB; g++) {
                float2 f = __half22float2(acc[g]);
                s.sbufA[q4][g][k] = facc[g] + f.x + f.y;
            }
        }
        __syncthreads();
        // ==== A reduce -> sphcH pairs (tid<256) ==============================
        if (tid < 256) {
            #pragma unroll
            for (int g = 0; g < GB; g++) {
                float phc = s.sbufA[0][g][k] + s.sbufA[1][g][k]
                          + s.sbufA[2][g][k] + s.sbufA[3][g][k];
                float nb = __shfl_down_sync(0xffffffffu, phc, 1);
                if (!(k & 1))
                    s.sphcH[g][k >> 1] = h2u(__floats2half2_rn(phc, nb));
            }
        }
        __syncthreads();

        float2 fIF[GB], fGO[GB];   // D accumulators
        if (tid < 512) {
            // ==== Phase B (warps 0-15): scores via tanh.f16x2 ================
            for (int t = warp; t < TM1; t += 16) {
                const uint2* Ev = (const uint2*)(g_EH + ((size_t)bs * TM1 + t) * 256);
                float sc[GB] = {0.f, 0.f, 0.f, 0.f};
                #pragma unroll
                for (int it = 0; it < 2; it++) {
                    int q = lane + (it << 5);
                    float4 wv = ((const float4*)s.w2s)[q];
                    #pragma unroll
                    for (int g = 0; g < GB; g++) {
                        uint2 e = Ev[g * (TM1 * 64) + q];
                        uint2 p = *(const uint2*)&s.sphcH[g][2 * q];
                        unsigned a0 = h2u(__hadd2(uh2(e.x), uh2(p.x)));
                        unsigned a1 = h2u(__hadd2(uh2(e.y), uh2(p.y)));
                        float2 f0 = __half22float2(uh2(tanh2u(a0)));
                        float2 f1 = __half22float2(uh2(tanh2u(a1)));
                        sc[g] += wv.x * f0.x + wv.y * f0.y + wv.z * f1.x + wv.w * f1.y;
                    }
                }
                #pragma unroll
                for (int o = 16; o; o >>= 1) {
                    #pragma unroll
                    for (int g = 0; g < GB; g++)
                        sc[g] += __shfl_xor_sync(0xffffffffu, sc[g], o);
                }
                if (lane == 0) {
                    #pragma unroll
                    for (int g = 0; g < GB; g++) s.sattn[g][t] = sc[g];
                }
            }
            asm volatile("bar.sync 1, 512;" ::: "memory");
            // ==== Phase C1 (warps 0-3): softmax + write attn rows ============
            if (warp < GB) {
                const int g = warp;
                float m = -1e30f;
                for (int t = lane; t < TM1; t += 32) m = fmaxf(m, s.sattn[g][t]);
                #pragma unroll
                for (int o = 16; o; o >>= 1) m = fmaxf(m, __shfl_xor_sync(0xffffffffu, m, o));
                float sum = 0.f;
                for (int t = lane; t < TM1; t += 32) {
                    float e = __expf(s.sattn[g][t] - m); s.sattn[g][t] = e; sum += e;
                }
                #pragma unroll
                for (int o = 16; o; o >>= 1) sum += __shfl_xor_sync(0xffffffffu, sum, o);
                const float inv = 1.f / sum;
                float* wrow = out + TB + ((size_t)(bs + g) * TM1 + step) * TM1;
                for (int t = lane; t < TM1; t += 32) {
                    float a = s.sattn[g][t] * inv; s.sattn[g][t] = a; wrow[t] = a;
                }
            }
        } else {
            // ==== Phase D (warps 16-31): gates = Whh @ h, HFMA2, j-split =====
            const int jh = (tid >> 8) & 1;   // 0: even j2, 1: odd j2
            __half2 hIF[GB], hGO[GB];
            #pragma unroll
            for (int g = 0; g < GB; g++) {
                hIF[g] = __float2half2_rn(0.f); hGO[g] = __float2half2_rn(0.f);
                fIF[g] = make_float2(0.f, 0.f); fGO[g] = make_float2(0.f, 0.f);
            }
            int i = 0;
            #pragma unroll
            for (int ch = 0; ch < 2; ch++) {          // cached chunks
                #pragma unroll
                for (int u = 0; u < 8; u++, i++) {
                    const int j2 = jh + 2 * i;
                    uint4 w = s.sWh[(j2 << 8) + k];
                    uint4 Ha = *(const uint4*)&s.shD2[j2][0];
                    uint4 Hb = *(const uint4*)&s.shD2[j2][2];
                    hIF[0] = __hfma2(uh2(w.x), uh2(Ha.x), hIF[0]);
                    hGO[0] = __hfma2(uh2(w.y), uh2(Ha.x), hGO[0]);
                    hIF[0] = __hfma2(uh2(w.z), uh2(Ha.y), hIF[0]);
                    hGO[0] = __hfma2(uh2(w.w), uh2(Ha.y), hGO[0]);
                    hIF[1] = __hfma2(uh2(w.x), uh2(Ha.z), hIF[1]);
                    hGO[1] = __hfma2(uh2(w.y), uh2(Ha.z), hGO[1]);
                    hIF[1] = __hfma2(uh2(w.z), uh2(Ha.w), hIF[1]);
                    hGO[1] = __hfma2(uh2(w.w), uh2(Ha.w), hGO[1]);
                    hIF[2] = __hfma2(uh2(w.x), uh2(Hb.x), hIF[2]);
                    hGO[2] = __hfma2(uh2(w.y), uh2(Hb.x), hGO[2]);
                    hIF[2] = __hfma2(uh2(w.z), uh2(Hb.y), hIF[2]);
                    hGO[2] = __hfma2(uh2(w.w), uh2(Hb.y), hGO[2]);
                    hIF[3] = __hfma2(uh2(w.x), uh2(Hb.z), hIF[3]);
                    hGO[3] = __hfma2(uh2(w.y), uh2(Hb.z), hGO[3]);
                    hIF[3] = __hfma2(uh2(w.z), uh2(Hb.w), hIF[3]);
                    hGO[3] = __hfma2(uh2(w.w), uh2(Hb.w), hGO[3]);
                }
                #pragma unroll
                for (int g = 0; g < GB; g++) {
                    float2 a = __half22float2(hIF[g]), b = __half22float2(hGO[g]);
                    fIF[g].x += a.x; fIF[g].y += a.y; fGO[g].x += b.x; fGO[g].y += b.y;
                    hIF[g] = __float2half2_rn(0.f); hGO[g] = __float2half2_rn(0.f);
                }
            }
            for (int ch = 0; ch < 6; ch++) {          // streamed chunks
                #pragma unroll
                for (int u = 0; u < 8; u++, i++) {
                    const int j2 = jh + 2 * i;
                    uint4 w = g_WhhH[(j2 << 8) + k];
                    uint4 Ha = *(const uint4*)&s.shD2[j2][0];
                    uint4 Hb = *(const uint4*)&s.shD2[j2][2];
                    hIF[0] = __hfma2(uh2(w.x), uh2(Ha.x), hIF[0]);
                    hGO[0] = __hfma2(uh2(w.y), uh2(Ha.x), hGO[0]);
                    hIF[0] = __hfma2(uh2(w.z), uh2(Ha.y), hIF[0]);
                    hGO[0] = __hfma2(uh2(w.w), uh2(Ha.y), hGO[0]);
                    hIF[1] = __hfma2(uh2(w.x), uh2(Ha.z), hIF[1]);
                    hGO[1] = __hfma2(uh2(w.y), uh2(Ha.z), hGO[1]);
                    hIF[1] = __hfma2(uh2(w.z), uh2(Ha.w), hIF[1]);
                    hGO[1] = __hfma2(uh2(w.w), uh2(Ha.w), hGO[1]);
                    hIF[2] = __hfma2(uh2(w.x), uh2(Hb.x), hIF[2]);
                    hGO[2] = __hfma2(uh2(w.y), uh2(Hb.x), hGO[2]);
                    hIF[2] = __hfma2(uh2(w.z), uh2(Hb.y), hIF[2]);
                    hGO[2] = __hfma2(uh2(w.w), uh2(Hb.y), hGO[2]);
                    hIF[3] = __hfma2(uh2(w.x), uh2(Hb.z), hIF[3]);
                    hGO[3] = __hfma2(uh2(w.y), uh2(Hb.z), hGO[3]);
                    hIF[3] = __hfma2(uh2(w.z), uh2(Hb.w), hIF[3]);
                    hGO[3] = __hfma2(uh2(w.w), uh2(Hb.w), hGO[3]);
                }
                #pragma unroll
                for (int g = 0; g < GB; g++) {
                    float2 a = __half22float2(hIF[g]), b = __half22float2(hGO[g]);
                    fIF[g].x += a.x; fIF[g].y += a.y; fGO[g].x += b.x; fGO[g].y += b.y;
                    hIF[g] = __float2half2_rn(0.f); hGO[g] = __float2half2_rn(0.f);
                }
            }
            if (jh == 1) {   // exchange odd-half partials (reuse sbufA)
                #pragma unroll
                for (int g = 0; g < GB; g++)
                    ((float4*)s.sbufA)[(g << 8) + k] =
                        make_float4(fIF[g].x, fIF[g].y, fGO[g].x, fGO[g].y);
            }
        }
        __syncthreads();   // join: sattn ready, D partials exchanged
        // ==== Phase C2 (tid<512): context partials, 2-way t split ============
        if (tid < 512) {
            const int g = tid >> 7, q = tid & 63, th = (tid >> 6) & 1;
            const uint2* ev = (const uint2*)(g_encH + ((size_t)(bs + g) * TM1) * 256) + q;
            ull acc01 = 0ull, acc23 = 0ull;
            const int t0 = th << 6, t1 = th ? TM1 : 64;
            #pragma unroll 4
            for (int t = t0; t < t1; t++) {
                float a = s.sattn[g][t];
                uint2 v = ev[(size_t)t << 6];
                float2 v01 = __half22float2(uh2(v.x)), v23 = __half22float2(uh2(v.y));
                ull A = pk2(a, a);
                fma2(acc01, A, pk2(v01.x, v01.y));
                fma2(acc23, A, pk2(v23.x, v23.y));
            }
            float2 a01 = up2(acc01), a23 = up2(acc23);
            s.sbufC[((g << 1) | th) << 6 | q] = make_float4(a01.x, a01.y, a23.x, a23.y);
        } else if (tid < 768) {
            // fold in odd-half D partials
            #pragma unroll
            for (int g = 0; g < GB; g++) {
                float4 p = ((const float4*)s.sbufA)[(g << 8) + k];
                fIF[g].x += p.x; fIF[g].y += p.y; fGO[g].x += p.z; fGO[g].y += p.w;
            }
        }
        __syncthreads();
        // ==== C2 reduce + y partials (warps 0-7) =============================
        if (warp < 8) {
            const int g = warp >> 1, hf = warp & 1;
            const int idx = (hf << 5) + lane;          // 0..63
            float4 o = s.sbufC[(g << 7) | idx];
            float4 p = s.sbufC[(g << 7) | 64 | idx];
            float4 c4 = make_float4(o.x + p.x, o.y + p.y, o.z + p.z, o.w + p.w);
            ((float4*)s.sctx[g])[idx] = c4;
            float4 wv = ((const float4*)s.wfcs)[idx];
            float v = wv.x * c4.x + wv.y * c4.y + wv.z * c4.z + wv.w * c4.w;
            #pragma unroll
            for (int o2 = 16; o2; o2 >>= 1) v += __shfl_xor_sync(0xffffffffu, v, o2);
            if (lane == 0) s.spart[(g << 1) + hf] = v;
        }
        __syncthreads();
        // ==== combine + state update (tid 512-767) ===========================
        if (tid >= 512 && tid < 768) {
            const float4 b4 = g_bih4[k], wi4 = g_wih4[k];
            float hnv[GB], cnv[GB];
            #pragma unroll
            for (int g = 0; g < GB; g++) {
                float y = bfc_v + wfc_y * s.syh[g][step] + s.spart[2 * g] + s.spart[2 * g + 1];
                float gi = fIF[g].x + b4.x + wi4.x * y;
                float gf = fIF[g].y + b4.y + wi4.y * y;
                float gg = fGO[g].x + b4.z + wi4.z * y;
                float go = fGO[g].y + b4.w + wi4.w * y;
                float cold = s.shc[g][256 + k];
                float cn = sigm(gf) * cold + sigm(gi) * tanh_acc(gg);
                float hn = sigm(go) * tanh_acc(cn);
                s.shc[g][256 + k] = cn;
                s.shc[g][k] = hn;
                hnv[g] = hn; cnv[g] = cn;
            }
            #pragma unroll
            for (int g = 0; g < GB; g++) {
                float hnb = __shfl_down_sync(0xffffffffu, hnv[g], 1);
                float cnb = __shfl_down_sync(0xffffffffu, cnv[g], 1);
                // splat h for D
                ((unsigned*)&s.shD2[k >> 1][g])[k & 1] =
                    h2u(__floats2half2_rn(hnv[g], hnv[g]));
                // h and c pairs for A
                if (!(k & 1)) {
                    const int slot = g * 2 + ((k >> 1) & 1);
                    s.sHA[k >> 2][slot]        = h2u(__floats2half2_rn(hnv[g], hnb));
                    s.sHA[64 + (k >> 2)][slot] = h2u(__floats2half2_rn(cnv[g], cnb));
                }
            }
        }
        __syncthreads();   // end of step
    }
    // ---- final: out[b] = b_fcf + Wfcf . [h ; context] -----------------------
    #pragma unroll
    for (int g = 0; g < GB; g++) {
        float v = (tid < 256)
                    ? (Wfcf[k] * s.shc[g][k] + Wfcf[256 + k] * s.sctx[g][k]) : 0.f;
        #pragma unroll
        for (int o = 16; o; o >>= 1) v += __shfl_down_sync(0xffffffffu, v, o);
        if (lane == 0) s.sred[warp] = v;
        __syncthreads();
        if (warp == 0) {
            float r = s.sred[lane];
            #pragma unroll
            for (int o = 16; o; o >>= 1) r += __shfl_down_sync(0xffffffffu, r, o);
            if (lane == 0) out[bs + g] = bfcf[0] + r;
        }
        __syncthreads();
    }
}

// ---------------- launch -----------------------------------------------------
extern "C" void kernel_launch(void* const* d_in, const int* in_sizes, int n_in,
                              void* d_out, int out_size) {
    const float* enc  = (const float*)d_in[0];
    const float* yh   = (const float*)d_in[1];
    const float* W1   = (const float*)d_in[2];
    const float* b1   = (const float*)d_in[3];
    const float* W2   = (const float*)d_in[4];
    // d_in[5] = b_attn2: softmax-invariant, unused
    const float* Wih  = (const float*)d_in[6];
    const float* Whh  = (const float*)d_in[7];
    const float* bih  = (const float*)d_in[8];
    const float* bhh  = (const float*)d_in[9];
    const float* Wfc  = (const float*)d_in[10];
    const float* bfc  = (const float*)d_in[11];
    const float* Wfcf = (const float*)d_in[12];
    const float* bfcf = (const float*)d_in[13];
    float* out = (float*)d_out;

    static bool attr_done = false;
    if (!attr_done) {
        cudaFuncSetAttribute(decoder_kernel,
                             cudaFuncAttributeMaxDynamicSharedMemorySize, sizeof(SmemT));
        attr_done = true;
    }
    prep_kernel<<<256, 256>>>(W1, Whh, bih, bhh, Wih, enc);
    e_gemm<<<dim3(1016, 4), 256>>>(enc, b1);
    decoder_kernel<<<NCTA, 1024, sizeof(SmemT)>>>(yh, W2, Wfc, bfc, Wfcf, bfcf, out);
}

// round 14
// speedup vs baseline: 1.1688x; 1.0078x over previous
#include <cuda_runtime.h>
#include <cuda_fp16.h>
#include <cstdint>

#define TB   512
#define TM1  127
#define ENCD 256
#define GB   4
#define NCTA (TB / GB)   // 128
#define NCA  22          // W1h chunks cached in smem (of 128)
#define NCB  32          // Whh chunks cached in smem (of 128)

typedef unsigned long long ull;

// ---------------- scratch (static device globals) ---------------------------
static __device__ __half g_EH[TB * TM1 * ENCD];    // E[b,t,k] fp16  (~33 MB)
static __device__ __half g_encH[TB * TM1 * ENCD];  // enc fp16 (epilogue ctx only)
static __device__ float  g_P[TB * TM1];            // P[b,t] = wfc . enc[b,t,:]
static __device__ uint2  g_W1h[128 * 256];         // (jb,k): half2(w_j0,w_j1), half2(w_j2,w_j3)
static __device__ uint4  g_WhhH[128 * 256];        // (j2,k): half2 (IF_j0, GO_j0, IF_j1, GO_j1)
static __device__ float  g_W1eT[256 * 256];        // [j][k]: W_attn1[k][512+j]
static __device__ float4 g_bih4[256];              // b_ih+b_hh per gate
static __device__ float4 g_wih4[256];              // W_ih per gate

// ---------------- dynamic smem layout ---------------------------------------
struct SmemT {
    uint4    sWh[NCB * 256];       // 131072 : Whh cache
    uint2    sW1[NCA * 256];       // 45056  : W1h cache
    uint2    shD2[128][4];         // 4096   : [j2][g] = (splat h_{2j2}, splat h_{2j2+1})
    unsigned sHA[128][8];          // 4096   : [jb][g*2+slot]; jb<64: h pairs, jb>=64: c pairs
    unsigned sphcH[GB][128];       // 2048   : half2 (phc_2m, phc_2m+1)
    float    sbufA[2][GB][256];    // 8192   : A partials (X-group only)
    float4   sbufD[1024];          // 16384  : D odd-half exchange / epilogue C2 partials
    float    shc[GB][512];         // 8192   : h | c (f32)
    float    sctx[GB][256];        // 4096   : epilogue only
    float    sattn[GB][128];       // 2048
    float    w2s[256];             // 1024
    float    syh[GB][128];         // 2048
    float    sP[GB][128];          // 2048
    float    sy[GB];               // 16
    float    sred[32];             // 128
};                                 // total ~230544 B

// ---------------- math helpers ----------------------------------------------
__device__ __forceinline__ float sigm(float x) { return 1.f / (1.f + __expf(-x)); }
__device__ __forceinline__ float tanh_acc(float x) {
    float e = __expf(2.f * x); return 1.f - 2.f / (e + 1.f);
}
__device__ __forceinline__ ull pk2(float x, float y) {
    ull r; asm("mov.b64 %0, {%1,%2};" : "=l"(r) : "f"(x), "f"(y)); return r;
}
__device__ __forceinline__ void fma2(ull& d, ull a, ull b) {
    asm("fma.rn.f32x2 %0, %1, %2, %0;" : "+l"(d) : "l"(a), "l"(b));
}
__device__ __forceinline__ float2 up2(ull v) {
    float2 f; asm("mov.b64 {%0,%1}, %2;" : "=f"(f.x), "=f"(f.y) : "l"(v)); return f;
}
__device__ __forceinline__ __half2 uh2(unsigned u) { return *(__half2*)&u; }
__device__ __forceinline__ unsigned h2u(__half2 h) { return *(unsigned*)&h; }
__device__ __forceinline__ unsigned tanh2u(unsigned x) {
    unsigned y; asm("tanh.approx.f16x2 %0, %1;" : "=r"(y) : "r"(x)); return y;
}

// ---------------- prep: packing / fp16 conversion ---------------------------
__global__ void prep_kernel(const float* __restrict__ W1, const float* __restrict__ Whh,
                            const float* __restrict__ bih, const float* __restrict__ bhh,
                            const float* __restrict__ Wih, const float* __restrict__ enc) {
    const int tid = blockIdx.x * blockDim.x + threadIdx.x;
    const int stride = gridDim.x * blockDim.x;
    for (int i = tid; i < 128 * 256; i += stride) {
        int jb = i >> 8, k = i & 255;
        const float* p = W1 + k * 768 + jb * 4;
        __half2 a = __floats2half2_rn(p[0], p[1]);
        __half2 b = __floats2half2_rn(p[2], p[3]);
        uint2 u; u.x = h2u(a); u.y = h2u(b);
        g_W1h[i] = u;
    }
    for (int i = tid; i < 256 * 256; i += stride) {
        int j = i >> 8, k = i & 255;
        g_W1eT[i] = W1[k * 768 + 512 + j];
    }
    for (int i = tid; i < 128 * 256; i += stride) {
        int j2 = i >> 8, k = i & 255;
        int j0 = j2 * 2, j1 = j0 + 1;
        __half2 a = __floats2half2_rn(Whh[k * 256 + j0],         Whh[(k + 256) * 256 + j0]);
        __half2 b = __floats2half2_rn(Whh[(k + 512) * 256 + j0], Whh[(k + 768) * 256 + j0]);
        __half2 c = __floats2half2_rn(Whh[k * 256 + j1],         Whh[(k + 256) * 256 + j1]);
        __half2 d = __floats2half2_rn(Whh[(k + 512) * 256 + j1], Whh[(k + 768) * 256 + j1]);
        uint4 u; u.x = h2u(a); u.y = h2u(b); u.z = h2u(c); u.w = h2u(d);
        g_WhhH[i] = u;
    }
    for (int i = tid; i < 256; i += stride) {
        g_bih4[i] = make_float4(bih[i] + bhh[i], bih[i + 256] + bhh[i + 256],
                                bih[i + 512] + bhh[i + 512], bih[i + 768] + bhh[i + 768]);
        g_wih4[i] = make_float4(Wih[i], Wih[i + 256], Wih[i + 512], Wih[i + 768]);
    }
    const int n = TB * TM1 * ENCD;
    for (int i = tid; i < n; i += stride) g_encH[i] = __float2half(enc[i]);
}

// ---------------- P[b,t] = wfc . enc[b,t,:] (f32) ----------------------------
__global__ void p_kernel(const float* __restrict__ enc, const float* __restrict__ Wfc) {
    const int w = (blockIdx.x * blockDim.x + threadIdx.x) >> 5;
    const int lane = threadIdx.x & 31;
    const int nw = (gridDim.x * blockDim.x) >> 5;
    for (int r = w; r < TB * TM1; r += nw) {
        const float4* e4 = (const float4*)(enc + (size_t)r * 256);
        float v = 0.f;
        #pragma unroll
        for (int i = 0; i < 2; i++) {
            float4 a = e4[lane + i * 32];
            float4 wv = ((const float4*)Wfc)[lane + i * 32];
            v += a.x * wv.x + a.y * wv.y + a.z * wv.z + a.w * wv.w;
        }
        #pragma unroll
        for (int o = 16; o; o >>= 1) v += __shfl_xor_sync(0xffffffffu, v, o);
        if (lane == 0) g_P[r] = v;
    }
}

// ---------------- E = enc @ W_e^T + b_attn1 (fp16 out) ----------------------
__global__ __launch_bounds__(256) void e_gemm(const float* __restrict__ A,
                                              const float* __restrict__ bias) {
    __shared__ float As[16][64];
    __shared__ float Bs[16][64];
    const int tid = threadIdx.x;
    const int row0 = blockIdx.x * 64;
    const int col0 = blockIdx.y * 64;
    const int tx = tid & 15, ty = tid >> 4;
    float acc[4][4] = {};
    for (int k0 = 0; k0 < 256; k0 += 16) {
        #pragma unroll
        for (int i = tid; i < 1024; i += 256) {
            int m = i >> 4, kk = i & 15;
            As[kk][m] = A[(size_t)(row0 + m) * 256 + k0 + kk];
        }
        {
            int kk = tid >> 4, n4 = tid & 15;
            ((float4*)&Bs[kk][0])[n4] =
                ((const float4*)&g_W1eT[(k0 + kk) * 256 + col0])[n4];
        }
        __syncthreads();
        #pragma unroll
        for (int kk = 0; kk < 16; kk++) {
            float4 av = ((const float4*)&As[kk][0])[ty];
            float4 bv = ((const float4*)&Bs[kk][0])[tx];
            acc[0][0] += av.x * bv.x; acc[0][1] += av.x * bv.y; acc[0][2] += av.x * bv.z; acc[0][3] += av.x * bv.w;
            acc[1][0] += av.y * bv.x; acc[1][1] += av.y * bv.y; acc[1][2] += av.y * bv.z; acc[1][3] += av.y * bv.w;
            acc[2][0] += av.z * bv.x; acc[2][1] += av.z * bv.y; acc[2][2] += av.z * bv.z; acc[2][3] += av.z * bv.w;
            acc[3][0] += av.w * bv.x; acc[3][1] += av.w * bv.y; acc[3][2] += av.w * bv.z; acc[3][3] += av.w * bv.w;
        }
        __syncthreads();
    }
    float4 bv = ((const float4*)(bias + col0))[tx];
    #pragma unroll
    for (int i = 0; i < 4; i++) {
        int row = row0 + ty * 4 + i;
        __half2 h01 = __floats2half2_rn(acc[i][0] + bv.x, acc[i][1] + bv.y);
        __half2 h23 = __floats2half2_rn(acc[i][2] + bv.z, acc[i][3] + bv.w);
        uint2 u; u.x = h2u(h01); u.y = h2u(h23);
        ((uint2*)(g_EH + (size_t)row * 256 + col0))[tx] = u;
    }
}

// ---------------- persistent decoder: X=attn warps 0-15, Y=lstm warps 16-31 --
__global__ __launch_bounds__(1024, 1) void decoder_kernel(
    const float* __restrict__ yhist, const float* __restrict__ w2,
    const float* __restrict__ bfc, const float* __restrict__ Wfc256,
    const float* __restrict__ Wfcf, const float* __restrict__ bfcf,
    float* __restrict__ out) {
    extern __shared__ char smem_raw[];
    SmemT& s = *(SmemT*)smem_raw;

    const int tid = threadIdx.x;
    const int lane = tid & 31, warp = tid >> 5;
    const int bs = blockIdx.x * GB;
    const int k = tid & 255;

    // ---- init --------------------------------------------------------------
    for (int i = tid; i < NCA * 256; i += 1024) s.sW1[i] = g_W1h[i];
    for (int i = tid; i < NCB * 256; i += 1024) s.sWh[i] = g_WhhH[i];
    ((unsigned*)s.sHA)[tid] = 0u;   // 1024 entries: h and c pair tables
    if (tid < 512) {
        int g = tid >> 7, t = tid & 127;
        if (t < TM1) {
            s.syh[g][t] = yhist[(bs + g) * TM1 + t];
            s.sP[g][t] = g_P[(bs + g) * TM1 + t];
        }
        ((uint2*)s.shD2)[tid] = make_uint2(0u, 0u);
        ((unsigned*)s.sphcH)[tid] = 0u;
    }
    if (tid < 256) {
        s.w2s[tid] = w2[tid];
        #pragma unroll
        for (int g = 0; g < GB; g++) { s.shc[g][tid] = 0.f; s.shc[g][256 + tid] = 0.f; }
    }
    const float wfc_y = Wfc256[0];   // Wfc[256]
    const float bfc_v = bfc[0];
    __syncthreads();

    for (int step = 0; step < TM1; step++) {
        float2 fIF[GB], fGO[GB];   // D accumulators (Y-group registers)
        if (tid < 512) {
            // ================= X group: A -> B -> C1 =========================
            // ---- Phase A: phc partials, HFMA2, 2-way jb split ---------------
            {
                const int q4 = tid >> 8;   // 0/1
                __half2 acc[GB];
                float facc[GB];
                #pragma unroll
                for (int g = 0; g < GB; g++) { acc[g] = __float2half2_rn(0.f); facc[g] = 0.f; }
                const int iC = (NCA - q4 + 1) >> 1;
                int i = 0;
                #pragma unroll 4
                for (; i < iC; i++) {
                    const int jb = q4 + 2 * i;
                    uint2 w = s.sW1[(jb << 8) + k];
                    #pragma unroll
                    for (int gg = 0; gg < GB; gg += 2) {
                        uint4 H = *(const uint4*)&s.sHA[jb][gg * 2];
                        acc[gg]     = __hfma2(uh2(w.x), uh2(H.x), acc[gg]);
                        acc[gg]     = __hfma2(uh2(w.y), uh2(H.y), acc[gg]);
                        acc[gg + 1] = __hfma2(uh2(w.x), uh2(H.z), acc[gg + 1]);
                        acc[gg + 1] = __hfma2(uh2(w.y), uh2(H.w), acc[gg + 1]);
                    }
                    if ((i & 3) == 3) {
                        #pragma unroll
                        for (int g = 0; g < GB; g++) {
                            float2 f = __half22float2(acc[g]);
                            facc[g] += f.x + f.y; acc[g] = __float2half2_rn(0.f);
                        }
                    }
                }
                #pragma unroll 4
                for (; i < 64; i++) {
                    const int jb = q4 + 2 * i;
                    uint2 w = g_W1h[(jb << 8) + k];
                    #pragma unroll
                    for (int gg = 0; gg < GB; gg += 2) {
                        uint4 H = *(const uint4*)&s.sHA[jb][gg * 2];
                        acc[gg]     = __hfma2(uh2(w.x), uh2(H.x), acc[gg]);
                        acc[gg]     = __hfma2(uh2(w.y), uh2(H.y), acc[gg]);
                        acc[gg + 1] = __hfma2(uh2(w.x), uh2(H.z), acc[gg + 1]);
                        acc[gg + 1] = __hfma2(uh2(w.y), uh2(H.w), acc[gg + 1]);
                    }
                    if ((i & 3) == 3) {
                        #pragma unroll
                        for (int g = 0; g < GB; g++) {
                            float2 f = __half22float2(acc[g]);
                            facc[g] += f.x + f.y; acc[g] = __float2half2_rn(0.f);
                        }
                    }
                }
                #pragma unroll
                for (int g = 0; g < GB; g++) {
                    float2 f = __half22float2(acc[g]);
                    s.sbufA[q4][g][k] = facc[g] + f.x + f.y;
                }
            }
            asm volatile("bar.sync 1, 512;" ::: "memory");
            // ---- A reduce -> sphcH pairs (tid<256) --------------------------
            if (tid < 256) {
                #pragma unroll
                for (int g = 0; g < GB; g++) {
                    float phc = s.sbufA[0][g][k] + s.sbufA[1][g][k];
                    float nb = __shfl_down_sync(0xffffffffu, phc, 1);
                    if (!(k & 1))
                        s.sphcH[g][k >> 1] = h2u(__floats2half2_rn(phc, nb));
                }
            }
            asm volatile("bar.sync 1, 512;" ::: "memory");
            // ---- Phase B: scores via tanh.f16x2 -----------------------------
            for (int t = warp; t < TM1; t += 16) {
                const uint2* Ev = (const uint2*)(g_EH + ((size_t)bs * TM1 + t) * 256);
                float sc[GB] = {0.f, 0.f, 0.f, 0.f};
                #pragma unroll
                for (int it = 0; it < 2; it++) {
                    int q = lane + (it << 5);
                    float4 wv = ((const float4*)s.w2s)[q];
                    #pragma unroll
                    for (int g = 0; g < GB; g++) {
                        uint2 e = Ev[g * (TM1 * 64) + q];
                        uint2 p = *(const uint2*)&s.sphcH[g][2 * q];
                        unsigned a0 = h2u(__hadd2(uh2(e.x), uh2(p.x)));
                        unsigned a1 = h2u(__hadd2(uh2(e.y), uh2(p.y)));
                        float2 f0 = __half22float2(uh2(tanh2u(a0)));
                        float2 f1 = __half22float2(uh2(tanh2u(a1)));
                        sc[g] += wv.x * f0.x + wv.y * f0.y + wv.z * f1.x + wv.w * f1.y;
                    }
                }
                #pragma unroll
                for (int o = 16; o; o >>= 1) {
                    #pragma unroll
                    for (int g = 0; g < GB; g++)
                        sc[g] += __shfl_xor_sync(0xffffffffu, sc[g], o);
                }
                if (lane == 0) {
                    #pragma unroll
                    for (int g = 0; g < GB; g++) s.sattn[g][t] = sc[g];
                }
            }
            asm volatile("bar.sync 1, 512;" ::: "memory");
            // ---- Phase C1 (warps 0-3): softmax + y via P + write attn -------
            if (warp < GB) {
                const int g = warp;
                float m = -1e30f;
                for (int t = lane; t < TM1; t += 32) m = fmaxf(m, s.sattn[g][t]);
                #pragma unroll
                for (int o = 16; o; o >>= 1) m = fmaxf(m, __shfl_xor_sync(0xffffffffu, m, o));
                float sum = 0.f, sumP = 0.f;
                for (int t = lane; t < TM1; t += 32) {
                    float e = __expf(s.sattn[g][t] - m);
                    s.sattn[g][t] = e;
                    sum += e;
                    sumP += e * s.sP[g][t];
                }
                #pragma unroll
                for (int o = 16; o; o >>= 1) {
                    sum  += __shfl_xor_sync(0xffffffffu, sum, o);
                    sumP += __shfl_xor_sync(0xffffffffu, sumP, o);
                }
                const float inv = 1.f / sum;
                if (lane == 0)
                    s.sy[g] = bfc_v + wfc_y * s.syh[g][step] + sumP * inv;
                float* wrow = out + TB + ((size_t)(bs + g) * TM1 + step) * TM1;
                for (int t = lane; t < TM1; t += 32) {
                    float a = s.sattn[g][t] * inv; s.sattn[g][t] = a; wrow[t] = a;
                }
            }
        } else {
            // ================= Y group: Phase D (Whh @ h), j-split ===========
            const int jh = (tid >> 8) & 1;   // 0: even j2, 1: odd j2
            __half2 hIF[GB], hGO[GB];
            #pragma unroll
            for (int g = 0; g < GB; g++) {
                hIF[g] = __float2half2_rn(0.f); hGO[g] = __float2half2_rn(0.f);
                fIF[g] = make_float2(0.f, 0.f); fGO[g] = make_float2(0.f, 0.f);
            }
            int i = 0;
            #pragma unroll
            for (int ch = 0; ch < 2; ch++) {          // cached chunks
                #pragma unroll
                for (int u = 0; u < 8; u++, i++) {
                    const int j2 = jh + 2 * i;
                    uint4 w = s.sWh[(j2 << 8) + k];
                    uint4 Ha = *(const uint4*)&s.shD2[j2][0];
                    uint4 Hb = *(const uint4*)&s.shD2[j2][2];
                    hIF[0] = __hfma2(uh2(w.x), uh2(Ha.x), hIF[0]);
                    hGO[0] = __hfma2(uh2(w.y), uh2(Ha.x), hGO[0]);
                    hIF[0] = __hfma2(uh2(w.z), uh2(Ha.y), hIF[0]);
                    hGO[0] = __hfma2(uh2(w.w), uh2(Ha.y), hGO[0]);
                    hIF[1] = __hfma2(uh2(w.x), uh2(Ha.z), hIF[1]);
                    hGO[1] = __hfma2(uh2(w.y), uh2(Ha.z), hGO[1]);
                    hIF[1] = __hfma2(uh2(w.z), uh2(Ha.w), hIF[1]);
                    hGO[1] = __hfma2(uh2(w.w), uh2(Ha.w), hGO[1]);
                    hIF[2] = __hfma2(uh2(w.x), uh2(Hb.x), hIF[2]);
                    hGO[2] = __hfma2(uh2(w.y), uh2(Hb.x), hGO[2]);
                    hIF[2] = __hfma2(uh2(w.z), uh2(Hb.y), hIF[2]);
                    hGO[2] = __hfma2(uh2(w.w), uh2(Hb.y), hGO[2]);
                    hIF[3] = __hfma2(uh2(w.x), uh2(Hb.z), hIF[3]);
                    hGO[3] = __hfma2(uh2(w.y), uh2(Hb.z), hGO[3]);
                    hIF[3] = __hfma2(uh2(w.z), uh2(Hb.w), hIF[3]);
                    hGO[3] = __hfma2(uh2(w.w), uh2(Hb.w), hGO[3]);
                }
                #pragma unroll
                for (int g = 0; g < GB; g++) {
                    float2 a = __half22float2(hIF[g]), b = __half22float2(hGO[g]);
                    fIF[g].x += a.x; fIF[g].y += a.y; fGO[g].x += b.x; fGO[g].y += b.y;
                    hIF[g] = __float2half2_rn(0.f); hGO[g] = __float2half2_rn(0.f);
                }
            }
            for (int ch = 0; ch < 6; ch++) {          // streamed chunks
                #pragma unroll
                for (int u = 0; u < 8; u++, i++) {
                    const int j2 = jh + 2 * i;
                    uint4 w = g_WhhH[(j2 << 8) + k];
                    uint4 Ha = *(const uint4*)&s.shD2[j2][0];
                    uint4 Hb = *(const uint4*)&s.shD2[j2][2];
                    hIF[0] = __hfma2(uh2(w.x), uh2(Ha.x), hIF[0]);
                    hGO[0] = __hfma2(uh2(w.y), uh2(Ha.x), hGO[0]);
                    hIF[0] = __hfma2(uh2(w.z), uh2(Ha.y), hIF[0]);
                    hGO[0] = __hfma2(uh2(w.w), uh2(Ha.y), hGO[0]);
                    hIF[1] = __hfma2(uh2(w.x), uh2(Ha.z), hIF[1]);
                    hGO[1] = __hfma2(uh2(w.y), uh2(Ha.z), hGO[1]);
                    hIF[1] = __hfma2(uh2(w.z), uh2(Ha.w), hIF[1]);
                    hGO[1] = __hfma2(uh2(w.w), uh2(Ha.w), hGO[1]);
                    hIF[2] = __hfma2(uh2(w.x), uh2(Hb.x), hIF[2]);
                    hGO[2] = __hfma2(uh2(w.y), uh2(Hb.x), hGO[2]);
                    hIF[2] = __hfma2(uh2(w.z), uh2(Hb.y), hIF[2]);
                    hGO[2] = __hfma2(uh2(w.w), uh2(Hb.y), hGO[2]);
                    hIF[3] = __hfma2(uh2(w.x), uh2(Hb.z), hIF[3]);
                    hGO[3] = __hfma2(uh2(w.y), uh2(Hb.z), hGO[3]);
                    hIF[3] = __hfma2(uh2(w.z), uh2(Hb.w), hIF[3]);
                    hGO[3] = __hfma2(uh2(w.w), uh2(Hb.w), hGO[3]);
                }
                #pragma unroll
                for (int g = 0; g < GB; g++) {
                    float2 a = __half22float2(hIF[g]), b = __half22float2(hGO[g]);
                    fIF[g].x += a.x; fIF[g].y += a.y; fGO[g].x += b.x; fGO[g].y += b.y;
                    hIF[g] = __float2half2_rn(0.f); hGO[g] = __float2half2_rn(0.f);
                }
            }
            if (jh == 1) {   // exchange odd-half partials
                #pragma unroll
                for (int g = 0; g < GB; g++)
                    s.sbufD[(g << 8) + k] =
                        make_float4(fIF[g].x, fIF[g].y, fGO[g].x, fGO[g].y);
            }
        }
        __syncthreads();   // join: y + attn ready (X), D partials exchanged (Y)
        // ==== combine + state update (tid 512-767) ===========================
        if (tid >= 512 && tid < 768) {
            const float4 b4 = g_bih4[k], wi4 = g_wih4[k];
            float hnv[GB], cnv[GB];
            #pragma unroll
            for (int g = 0; g < GB; g++) {
                float4 p = s.sbufD[(g << 8) + k];
                float y = s.sy[g];
                float gi = fIF[g].x + p.x + b4.x + wi4.x * y;
                float gf = fIF[g].y + p.y + b4.y + wi4.y * y;
                float gg = fGO[g].x + p.z + b4.z + wi4.z * y;
                float go = fGO[g].y + p.w + b4.w + wi4.w * y;
                float cold = s.shc[g][256 + k];
                float cn = sigm(gf) * cold + sigm(gi) * tanh_acc(gg);
                float hn = sigm(go) * tanh_acc(cn);
                s.shc[g][256 + k] = cn;
                s.shc[g][k] = hn;
                hnv[g] = hn; cnv[g] = cn;
            }
            #pragma unroll
            for (int g = 0; g < GB; g++) {
                float hnb = __shfl_down_sync(0xffffffffu, hnv[g], 1);
                float cnb = __shfl_down_sync(0xffffffffu, cnv[g], 1);
                // splat h for D
                ((unsigned*)&s.shD2[k >> 1][g])[k & 1] =
                    h2u(__floats2half2_rn(hnv[g], hnv[g]));
                // h and c pairs for A
                if (!(k & 1)) {
                    const int slot = g * 2 + ((k >> 1) & 1);
                    s.sHA[k >> 2][slot]        = h2u(__floats2half2_rn(hnv[g], hnb));
                    s.sHA[64 + (k >> 2)][slot] = h2u(__floats2half2_rn(cnv[g], cnb));
                }
            }
        }
        __syncthreads();   // h,c ready for next step
    }
    // ==== epilogue: ctx once (last step's attn), then final output ===========
    if (tid < 512) {
        const int g = tid >> 7, q = tid & 63, th = (tid >> 6) & 1;
        const uint2* ev = (const uint2*)(g_encH + ((size_t)(bs + g) * TM1) * 256) + q;
        ull acc01 = 0ull, acc23 = 0ull;
        const int t0 = th << 6, t1 = th ? TM1 : 64;
        #pragma unroll 4
        for (int t = t0; t < t1; t++) {
            float a = s.sattn[g][t];
            uint2 v = ev[(size_t)t << 6];
            float2 v01 = __half22float2(uh2(v.x)), v23 = __half22float2(uh2(v.y));
            ull A = pk2(a, a);
            fma2(acc01, A, pk2(v01.x, v01.y));
            fma2(acc23, A, pk2(v23.x, v23.y));
        }
        float2 a01 = up2(acc01), a23 = up2(acc23);
        s.sbufD[((g << 1) | th) << 6 | q] = make_float4(a01.x, a01.y, a23.x, a23.y);
    }
    __syncthreads();
    if (warp < 8) {
        const int g = warp >> 1, hf = warp & 1;
        const int idx = (hf << 5) + lane;          // 0..63
        float4 o = s.sbufD[(g << 7) | idx];
        float4 p = s.sbufD[(g << 7) | 64 | idx];
        ((float4*)s.sctx[g])[idx] =
            make_float4(o.x + p.x, o.y + p.y, o.z + p.z, o.w + p.w);
    }
    __syncthreads();
    #pragma unroll
    for (int g = 0; g < GB; g++) {
        float v = (tid < 256)
                    ? (Wfcf[k] * s.shc[g][k] + Wfcf[256 + k] * s.sctx[g][k]) : 0.f;
        #pragma unroll
        for (int o = 16; o; o >>= 1) v += __shfl_down_sync(0xffffffffu, v, o);
        if (lane == 0) s.sred[warp] = v;
        __syncthreads();
        if (warp == 0) {
            float r = s.sred[lane];
            #pragma unroll
            for (int o = 16; o; o >>= 1) r += __shfl_down_sync(0xffffffffu, r, o);
            if (lane == 0) out[bs + g] = bfcf[0] + r;
        }
        __syncthreads();
    }
}

// ---------------- launch -----------------------------------------------------
extern "C" void kernel_launch(void* const* d_in, const int* in_sizes, int n_in,
                              void* d_out, int out_size) {
    const float* enc  = (const float*)d_in[0];
    const float* yh   = (const float*)d_in[1];
    const float* W1   = (const float*)d_in[2];
    const float* b1   = (const float*)d_in[3];
    const float* W2   = (const float*)d_in[4];
    // d_in[5] = b_attn2: softmax-invariant, unused
    const float* Wih  = (const float*)d_in[6];
    const float* Whh  = (const float*)d_in[7];
    const float* bih  = (const float*)d_in[8];
    const float* bhh  = (const float*)d_in[9];
    const float* Wfc  = (const float*)d_in[10];
    const float* bfc  = (const float*)d_in[11];
    const float* Wfcf = (const float*)d_in[12];
    const float* bfcf = (const float*)d_in[13];
    float* out = (float*)d_out;

    static bool attr_done = false;
    if (!attr_done) {
        cudaFuncSetAttribute(decoder_kernel,
                             cudaFuncAttributeMaxDynamicSharedMemorySize, sizeof(SmemT));
        attr_done = true;
    }
    prep_kernel<<<256, 256>>>(W1, Whh, bih, bhh, Wih, enc);
    p_kernel<<<128, 256>>>(enc, Wfc);
    e_gemm<<<dim3(1016, 4), 256>>>(enc, b1);
    decoder_kernel<<<NCTA, 1024, sizeof(SmemT)>>>(yh, W2, bfc, Wfc + 256,
                                                  Wfcf, bfcf, out);
}

// round 16
// speedup vs baseline: 1.3391x; 1.1457x over previous
#include <cuda_runtime.h>
#include <cuda_fp16.h>
#include <cstdint>

#define TB   512
#define TM1  127
#define ENCD 256
#define GB   4
#define NCTA (TB / GB)   // 128
#define NCA  32          // W1h chunks cached in smem (of 128)
#define NCB  32          // Whh chunks cached in smem (of 128)

typedef unsigned long long ull;

// ---------------- scratch (static device globals) ---------------------------
static __device__ __half g_EH[TB * TM1 * ENCD];    // E[b,t,k] fp16  (~33 MB)
static __device__ __half g_encH[TB * TM1 * ENCD];  // enc fp16 (epilogue ctx only)
static __device__ float  g_P[TB * TM1];            // P[b,t] = wfc . enc[b,t,:]
static __device__ uint2  g_W1h[128 * 256];         // (jb,k): half2 pairs of W1hc
static __device__ uint4  g_WhhH[128 * 256];        // (j2,k): half2 (IF_j0,GO_j0,IF_j1,GO_j1)
static __device__ float  g_W1eT[256 * 256];        // [j][k]: W_attn1[k][512+j]
static __device__ float4 g_bih4[256];              // b_ih+b_hh per gate
static __device__ float4 g_wih4[256];              // W_ih per gate

// ---------------- dynamic smem layout ---------------------------------------
struct LaneT {
    unsigned sHA[128][4];     // 2048 : [jb][g*2+slot] pairs; jb<64: h, jb>=64: c
    uint4    shD[128];        // 2048 : [j2] = (g0 splat h_2j2, g0 h_2j2+1, g1 .., g1 ..)
    unsigned sphcH[2][128];   // 1024 : half2 (phc_2m, phc_2m+1)
    float    sattn[2][128];   // 1024
    float    sP[2][128];      // 1024
    float    syh[2][128];     // 1024
    float    shc[2][512];     // 4096 : h | c (f32)
    float    sctx[2][256];    // 2048 : epilogue
    float4   spart[8];        // 128  : B partials (sum0,sumP0,sum1,sumP1)
    float    sy[2];
    float    sinv[2];
    float    sred[2][16];     // 128
    float    pad[14];
};
struct SmemT {
    uint4  sWh[NCB * 256];    // 131072 : Whh cache (shared, read-only)
    uint2  sW1[NCA * 256];    // 65536  : W1h cache (shared, read-only)
    LaneT  lane[2];           // ~29.3 KB
    float  w2s[256];          // 1024
};                            // ~227 KB

// ---------------- math helpers ----------------------------------------------
__device__ __forceinline__ float sigm(float x) { return 1.f / (1.f + __expf(-x)); }
__device__ __forceinline__ float tanh_acc(float x) {
    float e = __expf(2.f * x); return 1.f - 2.f / (e + 1.f);
}
__device__ __forceinline__ ull pk2(float x, float y) {
    ull r; asm("mov.b64 %0, {%1,%2};" : "=l"(r) : "f"(x), "f"(y)); return r;
}
__device__ __forceinline__ void fma2(ull& d, ull a, ull b) {
    asm("fma.rn.f32x2 %0, %1, %2, %0;" : "+l"(d) : "l"(a), "l"(b));
}
__device__ __forceinline__ float2 up2(ull v) {
    float2 f; asm("mov.b64 {%0,%1}, %2;" : "=f"(f.x), "=f"(f.y) : "l"(v)); return f;
}
__device__ __forceinline__ __half2 uh2(unsigned u) { return *(__half2*)&u; }
__device__ __forceinline__ unsigned h2u(__half2 h) { return *(unsigned*)&h; }
__device__ __forceinline__ unsigned tanh2u(unsigned x) {
    unsigned y; asm("tanh.approx.f16x2 %0, %1;" : "=r"(y) : "r"(x)); return y;
}
__device__ __forceinline__ void barn(int id, int n) {
    asm volatile("bar.sync %0, %1;" :: "r"(id), "r"(n) : "memory");
}

// ---------------- prep: packing / fp16 conversion ---------------------------
__global__ void prep_kernel(const float* __restrict__ W1, const float* __restrict__ Whh,
                            const float* __restrict__ bih, const float* __restrict__ bhh,
                            const float* __restrict__ Wih, const float* __restrict__ enc) {
    const int tid = blockIdx.x * blockDim.x + threadIdx.x;
    const int stride = gridDim.x * blockDim.x;
    for (int i = tid; i < 128 * 256; i += stride) {
        int jb = i >> 8, k = i & 255;
        const float* p = W1 + k * 768 + jb * 4;
        __half2 a = __floats2half2_rn(p[0], p[1]);
        __half2 b = __floats2half2_rn(p[2], p[3]);
        uint2 u; u.x = h2u(a); u.y = h2u(b);
        g_W1h[i] = u;
    }
    for (int i = tid; i < 256 * 256; i += stride) {
        int j = i >> 8, k = i & 255;
        g_W1eT[i] = W1[k * 768 + 512 + j];
    }
    for (int i = tid; i < 128 * 256; i += stride) {
        int j2 = i >> 8, k = i & 255;
        int j0 = j2 * 2, j1 = j0 + 1;
        __half2 a = __floats2half2_rn(Whh[k * 256 + j0],         Whh[(k + 256) * 256 + j0]);
        __half2 b = __floats2half2_rn(Whh[(k + 512) * 256 + j0], Whh[(k + 768) * 256 + j0]);
        __half2 c = __floats2half2_rn(Whh[k * 256 + j1],         Whh[(k + 256) * 256 + j1]);
        __half2 d = __floats2half2_rn(Whh[(k + 512) * 256 + j1], Whh[(k + 768) * 256 + j1]);
        uint4 u; u.x = h2u(a); u.y = h2u(b); u.z = h2u(c); u.w = h2u(d);
        g_WhhH[i] = u;
    }
    for (int i = tid; i < 256; i += stride) {
        g_bih4[i] = make_float4(bih[i] + bhh[i], bih[i + 256] + bhh[i + 256],
                                bih[i + 512] + bhh[i + 512], bih[i + 768] + bhh[i + 768]);
        g_wih4[i] = make_float4(Wih[i], Wih[i + 256], Wih[i + 512], Wih[i + 768]);
    }
    const int n = TB * TM1 * ENCD;
    for (int i = tid; i < n; i += stride) g_encH[i] = __float2half(enc[i]);
}

// ---------------- P[b,t] = wfc . enc[b,t,:] (f32) ----------------------------
__global__ void p_kernel(const float* __restrict__ enc, const float* __restrict__ Wfc) {
    const int w = (blockIdx.x * blockDim.x + threadIdx.x) >> 5;
    const int lane = threadIdx.x & 31;
    const int nw = (gridDim.x * blockDim.x) >> 5;
    for (int r = w; r < TB * TM1; r += nw) {
        const float4* e4 = (const float4*)(enc + (size_t)r * 256);
        float v = 0.f;
        #pragma unroll
        for (int i = 0; i < 2; i++) {
            float4 a = e4[lane + i * 32];
            float4 wv = ((const float4*)Wfc)[lane + i * 32];
            v += a.x * wv.x + a.y * wv.y + a.z * wv.z + a.w * wv.w;
        }
        #pragma unroll
        for (int o = 16; o; o >>= 1) v += __shfl_xor_sync(0xffffffffu, v, o);
        if (lane == 0) g_P[r] = v;
    }
}

// ---------------- E = enc @ W_e^T + b_attn1 (fp16 out) ----------------------
__global__ __launch_bounds__(256) void e_gemm(const float* __restrict__ A,
                                              const float* __restrict__ bias) {
    __shared__ float As[16][64];
    __shared__ float Bs[16][64];
    const int tid = threadIdx.x;
    const int row0 = blockIdx.x * 64;
    const int col0 = blockIdx.y * 64;
    const int tx = tid & 15, ty = tid >> 4;
    float acc[4][4] = {};
    for (int k0 = 0; k0 < 256; k0 += 16) {
        #pragma unroll
        for (int i = tid; i < 1024; i += 256) {
            int m = i >> 4, kk = i & 15;
            As[kk][m] = A[(size_t)(row0 + m) * 256 + k0 + kk];
        }
        {
            int kk = tid >> 4, n4 = tid & 15;
            ((float4*)&Bs[kk][0])[n4] =
                ((const float4*)&g_W1eT[(k0 + kk) * 256 + col0])[n4];
        }
        __syncthreads();
        #pragma unroll
        for (int kk = 0; kk < 16; kk++) {
            float4 av = ((const float4*)&As[kk][0])[ty];
            float4 bv = ((const float4*)&Bs[kk][0])[tx];
            acc[0][0] += av.x * bv.x; acc[0][1] += av.x * bv.y; acc[0][2] += av.x * bv.z; acc[0][3] += av.x * bv.w;
            acc[1][0] += av.y * bv.x; acc[1][1] += av.y * bv.y; acc[1][2] += av.y * bv.z; acc[1][3] += av.y * bv.w;
            acc[2][0] += av.z * bv.x; acc[2][1] += av.z * bv.y; acc[2][2] += av.z * bv.z; acc[2][3] += av.z * bv.w;
            acc[3][0] += av.w * bv.x; acc[3][1] += av.w * bv.y; acc[3][2] += av.w * bv.z; acc[3][3] += av.w * bv.w;
        }
        __syncthreads();
    }
    float4 bv = ((const float4*)(bias + col0))[tx];
    #pragma unroll
    for (int i = 0; i < 4; i++) {
        int row = row0 + ty * 4 + i;
        __half2 h01 = __floats2half2_rn(acc[i][0] + bv.x, acc[i][1] + bv.y);
        __half2 h23 = __floats2half2_rn(acc[i][2] + bv.z, acc[i][3] + bv.w);
        uint2 u; u.x = h2u(h01); u.y = h2u(h23);
        ((uint2*)(g_EH + (size_t)row * 256 + col0))[tx] = u;
    }
}

// ---------------- persistent decoder: 2 independent 512-thread lanes ---------
__global__ __launch_bounds__(1024, 1) void decoder_kernel(
    const float* __restrict__ yhist, const float* __restrict__ w2,
    const float* __restrict__ bfc, const float* __restrict__ Wfc256,
    const float* __restrict__ Wfcf, const float* __restrict__ bfcf,
    float* __restrict__ out) {
    extern __shared__ char smem_raw[];
    SmemT& s = *(SmemT*)smem_raw;

    const int tid = threadIdx.x;
    const int l = tid >> 9;            // lane id 0/1
    const int lt = tid & 511;          // thread within lane
    const int lwarp = lt >> 5;         // 0..15 (0-7 = X, 8-15 = Y)
    const int lane32 = tid & 31;
    const int k = lt & 255;
    const bool isX = lt < 256;
    LaneT& L = s.lane[l];
    const int g0row = blockIdx.x * GB + 2 * l;
    const int idX = 1 + (l << 1), idL = 2 + (l << 1);

    // ---- init --------------------------------------------------------------
    for (int i = tid; i < NCA * 256; i += 1024) s.sW1[i] = g_W1h[i];
    for (int i = tid; i < NCB * 256; i += 1024) s.sWh[i] = g_WhhH[i];
    ((unsigned*)L.sHA)[lt] = 0u;
    ((unsigned*)L.shD)[lt] = 0u;
    ((float*)L.shc)[lt] = 0.f;
    ((float*)L.shc)[512 + lt] = 0.f;
    if (lt < 256) {
        ((unsigned*)L.sphcH)[lt] = 0u;
        int g = lt >> 7, t = lt & 127;
        if (t < TM1) {
            L.syh[g][t] = yhist[(g0row + g) * TM1 + t];
            L.sP[g][t] = g_P[(g0row + g) * TM1 + t];
        }
    }
    if (tid < 256) s.w2s[tid] = w2[tid];
    const float wfc_y = Wfc256[0];
    const float bfc_v = bfc[0];
    __syncthreads();

    for (int step = 0; step < TM1; step++) {
        if (isX) {
            // ==== Phase A: phc = W1hc[k,:].[h;c] for 2 g, full-j per thread ==
            {
                __half2 a0 = __float2half2_rn(0.f), a1 = a0;
                float f0 = 0.f, f1 = 0.f;
                int jb = 0;
                #pragma unroll 4
                for (; jb < NCA; jb++) {
                    uint2 w = s.sW1[(jb << 8) + k];
                    uint4 H = *(const uint4*)&L.sHA[jb][0];
                    a0 = __hfma2(uh2(w.x), uh2(H.x), a0);
                    a0 = __hfma2(uh2(w.y), uh2(H.y), a0);
                    a1 = __hfma2(uh2(w.x), uh2(H.z), a1);
                    a1 = __hfma2(uh2(w.y), uh2(H.w), a1);
                    if ((jb & 3) == 3) {
                        float2 u0 = __half22float2(a0), u1 = __half22float2(a1);
                        f0 += u0.x + u0.y; f1 += u1.x + u1.y;
                        a0 = __float2half2_rn(0.f); a1 = a0;
                    }
                }
                #pragma unroll 4
                for (; jb < 128; jb++) {
                    uint2 w = g_W1h[(jb << 8) + k];
                    uint4 H = *(const uint4*)&L.sHA[jb][0];
                    a0 = __hfma2(uh2(w.x), uh2(H.x), a0);
                    a0 = __hfma2(uh2(w.y), uh2(H.y), a0);
                    a1 = __hfma2(uh2(w.x), uh2(H.z), a1);
                    a1 = __hfma2(uh2(w.y), uh2(H.w), a1);
                    if ((jb & 3) == 3) {
                        float2 u0 = __half22float2(a0), u1 = __half22float2(a1);
                        f0 += u0.x + u0.y; f1 += u1.x + u1.y;
                        a0 = __float2half2_rn(0.f); a1 = a0;
                    }
                }
                float nb0 = __shfl_down_sync(0xffffffffu, f0, 1);
                float nb1 = __shfl_down_sync(0xffffffffu, f1, 1);
                if (!(k & 1)) {
                    L.sphcH[0][k >> 1] = h2u(__floats2half2_rn(f0, nb0));
                    L.sphcH[1][k >> 1] = h2u(__floats2half2_rn(f1, nb1));
                }
            }
            barn(idX, 256);
            // ==== Phase B: scores -> exp + warp partials (no max pass) =======
            {
                float sum0 = 0.f, sumP0 = 0.f, sum1 = 0.f, sumP1 = 0.f;
                for (int t = lwarp; t < TM1; t += 8) {
                    float sc0 = 0.f, sc1 = 0.f;
                    #pragma unroll
                    for (int it = 0; it < 2; it++) {
                        int q = lane32 + (it << 5);
                        float4 wv = ((const float4*)s.w2s)[q];
                        uint2 e0 = ((const uint2*)g_EH)[((size_t)(g0row)*TM1 + t) * 64 + q];
                        uint2 e1 = ((const uint2*)g_EH)[((size_t)(g0row + 1) * TM1 + t) * 64 + q];
                        uint2 p0 = *(const uint2*)&L.sphcH[0][2 * q];
                        uint2 p1 = *(const uint2*)&L.sphcH[1][2 * q];
                        unsigned b00 = h2u(__hadd2(uh2(e0.x), uh2(p0.x)));
                        unsigned b01 = h2u(__hadd2(uh2(e0.y), uh2(p0.y)));
                        unsigned b10 = h2u(__hadd2(uh2(e1.x), uh2(p1.x)));
                        unsigned b11 = h2u(__hadd2(uh2(e1.y), uh2(p1.y)));
                        float2 t00 = __half22float2(uh2(tanh2u(b00)));
                        float2 t01 = __half22float2(uh2(tanh2u(b01)));
                        float2 t10 = __half22float2(uh2(tanh2u(b10)));
                        float2 t11 = __half22float2(uh2(tanh2u(b11)));
                        sc0 += wv.x * t00.x + wv.y * t00.y + wv.z * t01.x + wv.w * t01.y;
                        sc1 += wv.x * t10.x + wv.y * t10.y + wv.z * t11.x + wv.w * t11.y;
                    }
                    #pragma unroll
                    for (int o = 16; o; o >>= 1) {
                        sc0 += __shfl_xor_sync(0xffffffffu, sc0, o);
                        sc1 += __shfl_xor_sync(0xffffffffu, sc1, o);
                    }
                    if (lane32 == 0) {
                        float e0 = __expf(sc0), e1 = __expf(sc1);
                        L.sattn[0][t] = e0; L.sattn[1][t] = e1;
                        sum0 += e0; sumP0 += e0 * L.sP[0][t];
                        sum1 += e1; sumP1 += e1 * L.sP[1][t];
                    }
                }
                if (lane32 == 0)
                    L.spart[lwarp] = make_float4(sum0, sumP0, sum1, sumP1);
            }
            barn(idX, 256);
            // ==== finalize y + inv (warp 0) ==================================
            if (lwarp == 0) {
                float4 p = (lane32 < 8) ? L.spart[lane32]
                                        : make_float4(0.f, 0.f, 0.f, 0.f);
                #pragma unroll
                for (int o = 4; o; o >>= 1) {
                    p.x += __shfl_xor_sync(0xffffffffu, p.x, o);
                    p.y += __shfl_xor_sync(0xffffffffu, p.y, o);
                    p.z += __shfl_xor_sync(0xffffffffu, p.z, o);
                    p.w += __shfl_xor_sync(0xffffffffu, p.w, o);
                }
                if (lane32 == 0) {
                    L.sy[0] = bfc_v + wfc_y * L.syh[0][step] + p.y / p.x;
                    L.sy[1] = bfc_v + wfc_y * L.syh[1][step] + p.w / p.z;
                    L.sinv[0] = 1.f / p.x;
                    L.sinv[1] = 1.f / p.z;
                }
            }
            barn(idL, 512);
            // ==== normalize + write attn rows (overlaps Y's combine) =========
            {
                int t = (lwarp << 4) + (lane32 & 15);
                if (lane32 < 16 && t < TM1) {
                    float a0 = L.sattn[0][t] * L.sinv[0];
                    float a1 = L.sattn[1][t] * L.sinv[1];
                    L.sattn[0][t] = a0; L.sattn[1][t] = a1;
                    out[TB + ((size_t)(g0row)*TM1 + step) * TM1 + t] = a0;
                    out[TB + ((size_t)(g0row + 1) * TM1 + step) * TM1 + t] = a1;
                }
            }
            barn(idL, 512);
        } else {
            // ==== Phase D: gates = Whh @ h for 2 g, full-j per thread ========
            __half2 hIF0 = __float2half2_rn(0.f), hGO0 = hIF0;
            __half2 hIF1 = hIF0, hGO1 = hIF0;
            float2 fIF0 = make_float2(0.f, 0.f), fGO0 = fIF0;
            float2 fIF1 = fIF0, fGO1 = fIF0;
            int j2 = 0;
            #pragma unroll 8
            for (; j2 < NCB; j2++) {
                uint4 w = s.sWh[(j2 << 8) + k];
                uint4 H = L.shD[j2];
                hIF0 = __hfma2(uh2(w.x), uh2(H.x), hIF0);
                hGO0 = __hfma2(uh2(w.y), uh2(H.x), hGO0);
                hIF0 = __hfma2(uh2(w.z), uh2(H.y), hIF0);
                hGO0 = __hfma2(uh2(w.w), uh2(H.y), hGO0);
                hIF1 = __hfma2(uh2(w.x), uh2(H.z), hIF1);
                hGO1 = __hfma2(uh2(w.y), uh2(H.z), hGO1);
                hIF1 = __hfma2(uh2(w.z), uh2(H.w), hIF1);
                hGO1 = __hfma2(uh2(w.w), uh2(H.w), hGO1);
                if ((j2 & 7) == 7) {
                    float2 a, b;
                    a = __half22float2(hIF0); b = __half22float2(hGO0);
                    fIF0.x += a.x; fIF0.y += a.y; fGO0.x += b.x; fGO0.y += b.y;
                    a = __half22float2(hIF1); b = __half22float2(hGO1);
                    fIF1.x += a.x; fIF1.y += a.y; fGO1.x += b.x; fGO1.y += b.y;
                    hIF0 = __float2half2_rn(0.f); hGO0 = hIF0; hIF1 = hIF0; hGO1 = hIF0;
                }
            }
            #pragma unroll 8
            for (; j2 < 128; j2++) {
                uint4 w = g_WhhH[(j2 << 8) + k];
                uint4 H = L.shD[j2];
                hIF0 = __hfma2(uh2(w.x), uh2(H.x), hIF0);
                hGO0 = __hfma2(uh2(w.y), uh2(H.x), hGO0);
                hIF0 = __hfma2(uh2(w.z), uh2(H.y), hIF0);
                hGO0 = __hfma2(uh2(w.w), uh2(H.y), hGO0);
                hIF1 = __hfma2(uh2(w.x), uh2(H.z), hIF1);
                hGO1 = __hfma2(uh2(w.y), uh2(H.z), hGO1);
                hIF1 = __hfma2(uh2(w.z), uh2(H.w), hIF1);
                hGO1 = __hfma2(uh2(w.w), uh2(H.w), hGO1);
                if ((j2 & 7) == 7) {
                    float2 a, b;
                    a = __half22float2(hIF0); b = __half22float2(hGO0);
                    fIF0.x += a.x; fIF0.y += a.y; fGO0.x += b.x; fGO0.y += b.y;
                    a = __half22float2(hIF1); b = __half22float2(hGO1);
                    fIF1.x += a.x; fIF1.y += a.y; fGO1.x += b.x; fGO1.y += b.y;
                    hIF0 = __float2half2_rn(0.f); hGO0 = hIF0; hIF1 = hIF0; hGO1 = hIF0;
                }
            }
            barn(idL, 512);   // join: y ready
            // ==== combine + state update =====================================
            {
                const float4 b4 = g_bih4[k], wi4 = g_wih4[k];
                float hnv[2], cnv[2];
                #pragma unroll
                for (int g = 0; g < 2; g++) {
                    float2 aIF = g ? fIF1 : fIF0;
                    float2 aGO = g ? fGO1 : fGO0;
                    float y = L.sy[g];
                    float gi = aIF.x + b4.x + wi4.x * y;
                    float gf = aIF.y + b4.y + wi4.y * y;
                    float gg = aGO.x + b4.z + wi4.z * y;
                    float go = aGO.y + b4.w + wi4.w * y;
                    float cold = L.shc[g][256 + k];
                    float cn = sigm(gf) * cold + sigm(gi) * tanh_acc(gg);
                    float hn = sigm(go) * tanh_acc(cn);
                    L.shc[g][256 + k] = cn;
                    L.shc[g][k] = hn;
                    hnv[g] = hn; cnv[g] = cn;
                }
                #pragma unroll
                for (int g = 0; g < 2; g++) {
                    float hnb = __shfl_down_sync(0xffffffffu, hnv[g], 1);
                    float cnb = __shfl_down_sync(0xffffffffu, cnv[g], 1);
                    ((unsigned*)&L.shD[k >> 1])[g * 2 + (k & 1)] =
                        h2u(__floats2half2_rn(hnv[g], hnv[g]));
                    if (!(k & 1)) {
                        const int slot = g * 2 + ((k >> 1) & 1);
                        L.sHA[k >> 2][slot]        = h2u(__floats2half2_rn(hnv[g], hnb));
                        L.sHA[64 + (k >> 2)][slot] = h2u(__floats2half2_rn(cnv[g], cnb));
                    }
                }
            }
            barn(idL, 512);   // state ready for next step
        }
    }
    // ==== epilogue ===========================================================
    __syncthreads();   // lanes may now reuse weight-cache smem
    {
        // ctx partials: per lane, 2 g x 4 t-quarters x 64 q
        const int g = lt >> 8, r = lt & 255, q = r & 63, th = (r >> 6) & 3;
        const uint2* ev = (const uint2*)g_encH + ((size_t)(g0row + g) * TM1) * 64 + q;
        ull acc01 = 0ull, acc23 = 0ull;
        const int t0 = th << 5, t1 = (th == 3) ? TM1 : (t0 + 32);
        for (int t = t0; t < t1; t++) {
            float a = L.sattn[g][t];
            uint2 v = ev[(size_t)t << 6];
            float2 v01 = __half22float2(uh2(v.x)), v23 = __half22float2(uh2(v.y));
            ull A = pk2(a, a);
            fma2(acc01, A, pk2(v01.x, v01.y));
            fma2(acc23, A, pk2(v23.x, v23.y));
        }
        float2 a01 = up2(acc01), a23 = up2(acc23);
        float4* epi = (float4*)s.sWh + l * 512;
        epi[((g << 2) | th) * 64 + q] = make_float4(a01.x, a01.y, a23.x, a23.y);
    }
    barn(idL, 512);
    if (lt < 128) {
        const int g = lt >> 6, q = lt & 63;
        const float4* epi = (const float4*)s.sWh + l * 512 + (g << 2) * 64;
        float4 a = epi[q], b = epi[64 + q], c = epi[128 + q], d = epi[192 + q];
        ((float4*)L.sctx[g])[q] = make_float4(a.x + b.x + c.x + d.x,
                                              a.y + b.y + c.y + d.y,
                                              a.z + b.z + c.z + d.z,
                                              a.w + b.w + c.w + d.w);
    }
    barn(idL, 512);
    #pragma unroll
    for (int g = 0; g < 2; g++) {
        float v = (lt < 256)
                    ? (Wfcf[k] * L.shc[g][k] + Wfcf[256 + k] * L.sctx[g][k]) : 0.f;
        #pragma unroll
        for (int o = 16; o; o >>= 1) v += __shfl_down_sync(0xffffffffu, v, o);
        if (lane32 == 0) L.sred[g][lwarp] = v;
    }
    barn(idL, 512);
    if (lwarp == 0) {
        float r0 = (lane32 < 16) ? L.sred[0][lane32] : 0.f;
        float r1 = (lane32 < 16) ? L.sred[1][lane32] : 0.f;
        #pragma unroll
        for (int o = 8; o; o >>= 1) {
            r0 += __shfl_down_sync(0xffffffffu, r0, o);
            r1 += __shfl_down_sync(0xffffffffu, r1, o);
        }
        if (lane32 == 0) {
            out[g0row] = bfcf[0] + r0;
            out[g0row + 1] = bfcf[0] + r1;
        }
    }
}

// ---------------- launch -----------------------------------------------------
extern "C" void kernel_launch(void* const* d_in, const int* in_sizes, int n_in,
                              void* d_out, int out_size) {
    const float* enc  = (const float*)d_in[0];
    const float* yh   = (const float*)d_in[1];
    const float* W1   = (const float*)d_in[2];
    const float* b1   = (const float*)d_in[3];
    const float* W2   = (const float*)d_in[4];
    // d_in[5] = b_attn2: softmax-invariant, unused
    const float* Wih  = (const float*)d_in[6];
    const float* Whh  = (const float*)d_in[7];
    const float* bih  = (const float*)d_in[8];
    const float* bhh  = (const float*)d_in[9];
    const float* Wfc  = (const float*)d_in[10];
    const float* bfc  = (const float*)d_in[11];
    const float* Wfcf = (const float*)d_in[12];
    const float* bfcf = (const float*)d_in[13];
    float* out = (float*)d_out;

    static bool attr_done = false;
    if (!attr_done) {
        cudaFuncSetAttribute(decoder_kernel,
                             cudaFuncAttributeMaxDynamicSharedMemorySize, sizeof(SmemT));
        attr_done = true;
    }
    prep_kernel<<<256, 256>>>(W1, Whh, bih, bhh, Wih, enc);
    p_kernel<<<128, 256>>>(enc, Wfc);
    e_gemm<<<dim3(1016, 4), 256>>>(enc, b1);
    decoder_kernel<<<NCTA, 1024, sizeof(SmemT)>>>(yh, W2, bfc, Wfc + 256,
                                                  Wfcf, bfcf, out);
}

// round 17
// speedup vs baseline: 1.3926x; 1.0400x over previous
#include <cuda_runtime.h>
#include <cuda_fp16.h>
#include <cstdint>

#define TB   512
#define TM1  127
#define ENCD 256
#define GB   4
#define NCTA (TB / GB)   // 128
#define NCAP 16          // W1h jb-PAIR chunks cached in smem (of 64)
#define NCB  32          // Whh chunks cached in smem (of 128)

typedef unsigned long long ull;

// ---------------- scratch (static device globals) ---------------------------
static __device__ __half g_EH[TB * TM1 * ENCD];    // E[b,t,k] fp16  (~33 MB)
static __device__ __half g_encH[TB * TM1 * ENCD];  // enc fp16 (epilogue ctx only)
static __device__ float  g_P[TB * TM1];            // P[b,t] = wfc . enc[b,t,:]
static __device__ uint4  g_W1h4[64 * 256];         // (jp,k): half2 pairs of W1hc, 8 j per row
static __device__ uint4  g_WhhH[128 * 256];        // (j2,k): half2 (IF_j0,GO_j0,IF_j1,GO_j1)
static __device__ float  g_W1eT[256 * 256];        // [j][k]: W_attn1[k][512+j]
static __device__ float4 g_bih4[256];              // b_ih+b_hh per gate
static __device__ float4 g_wih4[256];              // W_ih per gate

// ---------------- dynamic smem layout ---------------------------------------
struct LaneT {
    unsigned sHA[128][4];     // 2048 : [jb][g*2+slot] pairs; jb<64: h, jb>=64: c
    uint4    shD[128];        // 2048 : [j2] = (g0 splat h_2j2, g0 h_2j2+1, g1 .., g1 ..)
    unsigned sphcH[2][128];   // 1024 : half2 (phc_2m, phc_2m+1), 16B-aligned rows
    float    sattn[2][128];   // 1024
    float    sP[2][128];      // 1024
    float    syh[2][128];     // 1024
    float    shc[2][512];     // 4096 : h | c (f32)
    float    sctx[2][256];    // 2048 : epilogue
    float4   spart[8];        // 128  : B partials (sum0,sumP0,sum1,sumP1)
    float    sy[2];
    float    sinv[2];
    float    sred[2][16];     // 128
    float    pad[14];
};
struct SmemT {
    uint4  sWh[NCB * 256];    // 131072 : Whh cache (shared, read-only)
    uint4  sW1[NCAP * 256];   // 65536  : W1h pair cache (shared, read-only)
    LaneT  lane[2];           // ~29.3 KB
    float  w2s[256];          // 1024
};                            // ~227 KB

// ---------------- math helpers ----------------------------------------------
__device__ __forceinline__ float sigm(float x) { return 1.f / (1.f + __expf(-x)); }
__device__ __forceinline__ float tanh_acc(float x) {
    float e = __expf(2.f * x); return 1.f - 2.f / (e + 1.f);
}
__device__ __forceinline__ ull pk2(float x, float y) {
    ull r; asm("mov.b64 %0, {%1,%2};" : "=l"(r) : "f"(x), "f"(y)); return r;
}
__device__ __forceinline__ void fma2(ull& d, ull a, ull b) {
    asm("fma.rn.f32x2 %0, %1, %2, %0;" : "+l"(d) : "l"(a), "l"(b));
}
__device__ __forceinline__ float2 up2(ull v) {
    float2 f; asm("mov.b64 {%0,%1}, %2;" : "=f"(f.x), "=f"(f.y) : "l"(v)); return f;
}
__device__ __forceinline__ __half2 uh2(unsigned u) { return *(__half2*)&u; }
__device__ __forceinline__ unsigned h2u(__half2 h) { return *(unsigned*)&h; }
__device__ __forceinline__ unsigned tanh2u(unsigned x) {
    unsigned y; asm("tanh.approx.f16x2 %0, %1;" : "=r"(y) : "r"(x)); return y;
}
__device__ __forceinline__ void barn(int id, int n) {
    asm volatile("bar.sync %0, %1;" :: "r"(id), "r"(n) : "memory");
}

// ---------------- prep: packing / fp16 conversion ---------------------------
__global__ void prep_kernel(const float* __restrict__ W1, const float* __restrict__ Whh,
                            const float* __restrict__ bih, const float* __restrict__ bhh,
                            const float* __restrict__ Wih, const float* __restrict__ enc) {
    const int tid = blockIdx.x * blockDim.x + threadIdx.x;
    const int stride = gridDim.x * blockDim.x;
    for (int i = tid; i < 64 * 256; i += stride) {
        int jp = i >> 8, k = i & 255;
        const float* p = W1 + k * 768 + jp * 8;
        uint4 u;
        u.x = h2u(__floats2half2_rn(p[0], p[1]));
        u.y = h2u(__floats2half2_rn(p[2], p[3]));
        u.z = h2u(__floats2half2_rn(p[4], p[5]));
        u.w = h2u(__floats2half2_rn(p[6], p[7]));
        g_W1h4[i] = u;
    }
    for (int i = tid; i < 256 * 256; i += stride) {
        int j = i >> 8, k = i & 255;
        g_W1eT[i] = W1[k * 768 + 512 + j];
    }
    for (int i = tid; i < 128 * 256; i += stride) {
        int j2 = i >> 8, k = i & 255;
        int j0 = j2 * 2, j1 = j0 + 1;
        uint4 u;
        u.x = h2u(__floats2half2_rn(Whh[k * 256 + j0],         Whh[(k + 256) * 256 + j0]));
        u.y = h2u(__floats2half2_rn(Whh[(k + 512) * 256 + j0], Whh[(k + 768) * 256 + j0]));
        u.z = h2u(__floats2half2_rn(Whh[k * 256 + j1],         Whh[(k + 256) * 256 + j1]));
        u.w = h2u(__floats2half2_rn(Whh[(k + 512) * 256 + j1], Whh[(k + 768) * 256 + j1]));
        g_WhhH[i] = u;
    }
    for (int i = tid; i < 256; i += stride) {
        g_bih4[i] = make_float4(bih[i] + bhh[i], bih[i + 256] + bhh[i + 256],
                                bih[i + 512] + bhh[i + 512], bih[i + 768] + bhh[i + 768]);
        g_wih4[i] = make_float4(Wih[i], Wih[i + 256], Wih[i + 512], Wih[i + 768]);
    }
    const int n = TB * TM1 * ENCD;
    for (int i = tid; i < n; i += stride) g_encH[i] = __float2half(enc[i]);
}

// ---------------- P[b,t] = wfc . enc[b,t,:] (f32) ----------------------------
__global__ void p_kernel(const float* __restrict__ enc, const float* __restrict__ Wfc) {
    const int w = (blockIdx.x * blockDim.x + threadIdx.x) >> 5;
    const int lane = threadIdx.x & 31;
    const int nw = (gridDim.x * blockDim.x) >> 5;
    for (int r = w; r < TB * TM1; r += nw) {
        const float4* e4 = (const float4*)(enc + (size_t)r * 256);
        float v = 0.f;
        #pragma unroll
        for (int i = 0; i < 2; i++) {
            float4 a = e4[lane + i * 32];
            float4 wv = ((const float4*)Wfc)[lane + i * 32];
            v += a.x * wv.x + a.y * wv.y + a.z * wv.z + a.w * wv.w;
        }
        #pragma unroll
        for (int o = 16; o; o >>= 1) v += __shfl_xor_sync(0xffffffffu, v, o);
        if (lane == 0) g_P[r] = v;
    }
}

// ---------------- E = enc @ W_e^T + b_attn1 (fp16 out) ----------------------
__global__ __launch_bounds__(256) void e_gemm(const float* __restrict__ A,
                                              const float* __restrict__ bias) {
    __shared__ float As[16][64];
    __shared__ float Bs[16][64];
    const int tid = threadIdx.x;
    const int row0 = blockIdx.x * 64;
    const int col0 = blockIdx.y * 64;
    const int tx = tid & 15, ty = tid >> 4;
    float acc[4][4] = {};
    for (int k0 = 0; k0 < 256; k0 += 16) {
        #pragma unroll
        for (int i = tid; i < 1024; i += 256) {
            int m = i >> 4, kk = i & 15;
            As[kk][m] = A[(size_t)(row0 + m) * 256 + k0 + kk];
        }
        {
            int kk = tid >> 4, n4 = tid & 15;
            ((float4*)&Bs[kk][0])[n4] =
                ((const float4*)&g_W1eT[(k0 + kk) * 256 + col0])[n4];
        }
        __syncthreads();
        #pragma unroll
        for (int kk = 0; kk < 16; kk++) {
            float4 av = ((const float4*)&As[kk][0])[ty];
            float4 bv = ((const float4*)&Bs[kk][0])[tx];
            acc[0][0] += av.x * bv.x; acc[0][1] += av.x * bv.y; acc[0][2] += av.x * bv.z; acc[0][3] += av.x * bv.w;
            acc[1][0] += av.y * bv.x; acc[1][1] += av.y * bv.y; acc[1][2] += av.y * bv.z; acc[1][3] += av.y * bv.w;
            acc[2][0] += av.z * bv.x; acc[2][1] += av.z * bv.y; acc[2][2] += av.z * bv.z; acc[2][3] += av.z * bv.w;
            acc[3][0] += av.w * bv.x; acc[3][1] += av.w * bv.y; acc[3][2] += av.w * bv.z; acc[3][3] += av.w * bv.w;
        }
        __syncthreads();
    }
    float4 bv = ((const float4*)(bias + col0))[tx];
    #pragma unroll
    for (int i = 0; i < 4; i++) {
        int row = row0 + ty * 4 + i;
        __half2 h01 = __floats2half2_rn(acc[i][0] + bv.x, acc[i][1] + bv.y);
        __half2 h23 = __floats2half2_rn(acc[i][2] + bv.z, acc[i][3] + bv.w);
        uint2 u; u.x = h2u(h01); u.y = h2u(h23);
        ((uint2*)(g_EH + (size_t)row * 256 + col0))[tx] = u;
    }
}

// ---------------- persistent decoder: 2 independent 512-thread lanes ---------
__global__ __launch_bounds__(1024, 1) void decoder_kernel(
    const float* __restrict__ yhist, const float* __restrict__ w2,
    const float* __restrict__ bfc, const float* __restrict__ Wfc256,
    const float* __restrict__ Wfcf, const float* __restrict__ bfcf,
    float* __restrict__ out) {
    extern __shared__ char smem_raw[];
    SmemT& s = *(SmemT*)smem_raw;

    const int tid = threadIdx.x;
    const int l = tid >> 9;            // lane id 0/1
    const int lt = tid & 511;          // thread within lane
    const int lwarp = lt >> 5;         // 0..15 (0-7 = X, 8-15 = Y)
    const int lane32 = tid & 31;
    const int k = lt & 255;
    const bool isX = lt < 256;
    LaneT& L = s.lane[l];
    const int g0row = blockIdx.x * GB + 2 * l;
    const int idX = 1 + (l << 1), idL = 2 + (l << 1);

    // ---- init --------------------------------------------------------------
    for (int i = tid; i < NCAP * 256; i += 1024) s.sW1[i] = g_W1h4[i];
    for (int i = tid; i < NCB * 256; i += 1024) s.sWh[i] = g_WhhH[i];
    ((unsigned*)L.sHA)[lt] = 0u;
    ((unsigned*)L.shD)[lt] = 0u;
    ((float*)L.shc)[lt] = 0.f;
    ((float*)L.shc)[512 + lt] = 0.f;
    if (lt < 256) {
        ((unsigned*)L.sphcH)[lt] = 0u;
        int g = lt >> 7, t = lt & 127;
        if (t < TM1) {
            L.syh[g][t] = yhist[(g0row + g) * TM1 + t];
            L.sP[g][t] = g_P[(g0row + g) * TM1 + t];
        }
    }
    if (tid < 256) s.w2s[tid] = w2[tid];
    const float wfc_y = Wfc256[0];
    const float bfc_v = bfc[0];
    __syncthreads();

    for (int step = 0; step < TM1; step++) {
        if (isX) {
            // ==== Phase A: phc = W1hc[k,:].[h;c] for 2 g, jb-pair loads ======
            {
                __half2 a0 = __float2half2_rn(0.f), a1 = a0;
                float f0 = 0.f, f1 = 0.f;
                int jp = 0;
                #pragma unroll 2
                for (; jp < NCAP; jp++) {
                    uint4 w = s.sW1[(jp << 8) + k];
                    uint4 Ha = *(const uint4*)&L.sHA[2 * jp][0];
                    uint4 Hb = *(const uint4*)&L.sHA[2 * jp + 1][0];
                    a0 = __hfma2(uh2(w.x), uh2(Ha.x), a0);
                    a0 = __hfma2(uh2(w.y), uh2(Ha.y), a0);
                    a1 = __hfma2(uh2(w.x), uh2(Ha.z), a1);
                    a1 = __hfma2(uh2(w.y), uh2(Ha.w), a1);
                    a0 = __hfma2(uh2(w.z), uh2(Hb.x), a0);
                    a0 = __hfma2(uh2(w.w), uh2(Hb.y), a0);
                    a1 = __hfma2(uh2(w.z), uh2(Hb.z), a1);
                    a1 = __hfma2(uh2(w.w), uh2(Hb.w), a1);
                    if (jp & 1) {
                        float2 u0 = __half22float2(a0), u1 = __half22float2(a1);
                        f0 += u0.x + u0.y; f1 += u1.x + u1.y;
                        a0 = __float2half2_rn(0.f); a1 = a0;
                    }
                }
                #pragma unroll 4
                for (; jp < 64; jp++) {
                    uint4 w = g_W1h4[(jp << 8) + k];
                    uint4 Ha = *(const uint4*)&L.sHA[2 * jp][0];
                    uint4 Hb = *(const uint4*)&L.sHA[2 * jp + 1][0];
                    a0 = __hfma2(uh2(w.x), uh2(Ha.x), a0);
                    a0 = __hfma2(uh2(w.y), uh2(Ha.y), a0);
                    a1 = __hfma2(uh2(w.x), uh2(Ha.z), a1);
                    a1 = __hfma2(uh2(w.y), uh2(Ha.w), a1);
                    a0 = __hfma2(uh2(w.z), uh2(Hb.x), a0);
                    a0 = __hfma2(uh2(w.w), uh2(Hb.y), a0);
                    a1 = __hfma2(uh2(w.z), uh2(Hb.z), a1);
                    a1 = __hfma2(uh2(w.w), uh2(Hb.w), a1);
                    if (jp & 1) {
                        float2 u0 = __half22float2(a0), u1 = __half22float2(a1);
                        f0 += u0.x + u0.y; f1 += u1.x + u1.y;
                        a0 = __float2half2_rn(0.f); a1 = a0;
                    }
                }
                float nb0 = __shfl_down_sync(0xffffffffu, f0, 1);
                float nb1 = __shfl_down_sync(0xffffffffu, f1, 1);
                if (!(k & 1)) {
                    L.sphcH[0][k >> 1] = h2u(__floats2half2_rn(f0, nb0));
                    L.sphcH[1][k >> 1] = h2u(__floats2half2_rn(f1, nb1));
                }
            }
            barn(idX, 256);
            // ==== Phase B: whole E row per warp-iter, f32 score accum ========
            {
                float sum0 = 0.f, sumP0 = 0.f, sum1 = 0.f, sumP1 = 0.f;
                const uint4 p0 = *(const uint4*)&L.sphcH[0][4 * lane32];
                const uint4 p1 = *(const uint4*)&L.sphcH[1][4 * lane32];
                const float4 wva = ((const float4*)s.w2s)[2 * lane32];
                const float4 wvb = ((const float4*)s.w2s)[2 * lane32 + 1];
                for (int t = lwarp; t < TM1; t += 8) {
                    uint4 e0 = ((const uint4*)g_EH)[((size_t)(g0row)*TM1 + t) * 32 + lane32];
                    uint4 e1 = ((const uint4*)g_EH)[((size_t)(g0row + 1) * TM1 + t) * 32 + lane32];
                    unsigned q00 = tanh2u(h2u(__hadd2(uh2(e0.x), uh2(p0.x))));
                    unsigned q01 = tanh2u(h2u(__hadd2(uh2(e0.y), uh2(p0.y))));
                    unsigned q02 = tanh2u(h2u(__hadd2(uh2(e0.z), uh2(p0.z))));
                    unsigned q03 = tanh2u(h2u(__hadd2(uh2(e0.w), uh2(p0.w))));
                    unsigned q10 = tanh2u(h2u(__hadd2(uh2(e1.x), uh2(p1.x))));
                    unsigned q11 = tanh2u(h2u(__hadd2(uh2(e1.y), uh2(p1.y))));
                    unsigned q12 = tanh2u(h2u(__hadd2(uh2(e1.z), uh2(p1.z))));
                    unsigned q13 = tanh2u(h2u(__hadd2(uh2(e1.w), uh2(p1.w))));
                    float2 f00 = __half22float2(uh2(q00)), f01 = __half22float2(uh2(q01));
                    float2 f02 = __half22float2(uh2(q02)), f03 = __half22float2(uh2(q03));
                    float2 f10 = __half22float2(uh2(q10)), f11 = __half22float2(uh2(q11));
                    float2 f12 = __half22float2(uh2(q12)), f13 = __half22float2(uh2(q13));
                    float sc0 = f00.x * wva.x + f00.y * wva.y + f01.x * wva.z + f01.y * wva.w
                              + f02.x * wvb.x + f02.y * wvb.y + f03.x * wvb.z + f03.y * wvb.w;
                    float sc1 = f10.x * wva.x + f10.y * wva.y + f11.x * wva.z + f11.y * wva.w
                              + f12.x * wvb.x + f12.y * wvb.y + f13.x * wvb.z + f13.y * wvb.w;
                    #pragma unroll
                    for (int o = 16; o; o >>= 1) {
                        sc0 += __shfl_xor_sync(0xffffffffu, sc0, o);
                        sc1 += __shfl_xor_sync(0xffffffffu, sc1, o);
                    }
                    if (lane32 == 0) {
                        float e0s = __expf(sc0), e1s = __expf(sc1);
                        L.sattn[0][t] = e0s; L.sattn[1][t] = e1s;
                        sum0 += e0s; sumP0 += e0s * L.sP[0][t];
                        sum1 += e1s; sumP1 += e1s * L.sP[1][t];
                    }
                }
                if (lane32 == 0)
                    L.spart[lwarp] = make_float4(sum0, sumP0, sum1, sumP1);
            }
            barn(idX, 256);
            // ==== finalize y + inv (warp 0) ==================================
            if (lwarp == 0) {
                float4 p = (lane32 < 8) ? L.spart[lane32]
                                        : make_float4(0.f, 0.f, 0.f, 0.f);
                #pragma unroll
                for (int o = 4; o; o >>= 1) {
                    p.x += __shfl_xor_sync(0xffffffffu, p.x, o);
                    p.y += __shfl_xor_sync(0xffffffffu, p.y, o);
                    p.z += __shfl_xor_sync(0xffffffffu, p.z, o);
                    p.w += __shfl_xor_sync(0xffffffffu, p.w, o);
                }
                if (lane32 == 0) {
                    L.sy[0] = bfc_v + wfc_y * L.syh[0][step] + p.y / p.x;
                    L.sy[1] = bfc_v + wfc_y * L.syh[1][step] + p.w / p.z;
                    L.sinv[0] = 1.f / p.x;
                    L.sinv[1] = 1.f / p.z;
                }
            }
            barn(idL, 512);
            // ==== normalize + write attn rows (overlaps Y's combine) =========
            {
                int t = (lwarp << 4) + (lane32 & 15);
                if (lane32 < 16 && t < TM1) {
                    float a0 = L.sattn[0][t] * L.sinv[0];
                    float a1 = L.sattn[1][t] * L.sinv[1];
                    L.sattn[0][t] = a0; L.sattn[1][t] = a1;
                    out[TB + ((size_t)(g0row)*TM1 + step) * TM1 + t] = a0;
                    out[TB + ((size_t)(g0row + 1) * TM1 + step) * TM1 + t] = a1;
                }
            }
            barn(idL, 512);
        } else {
            // ==== Phase D: gates = Whh @ h for 2 g, full-j per thread ========
            __half2 hIF0 = __float2half2_rn(0.f), hGO0 = hIF0;
            __half2 hIF1 = hIF0, hGO1 = hIF0;
            float2 fIF0 = make_float2(0.f, 0.f), fGO0 = fIF0;
            float2 fIF1 = fIF0, fGO1 = fIF0;
            int j2 = 0;
            #pragma unroll 8
            for (; j2 < NCB; j2++) {
                uint4 w = s.sWh[(j2 << 8) + k];
                uint4 H = L.shD[j2];
                hIF0 = __hfma2(uh2(w.x), uh2(H.x), hIF0);
                hGO0 = __hfma2(uh2(w.y), uh2(H.x), hGO0);
                hIF0 = __hfma2(uh2(w.z), uh2(H.y), hIF0);
                hGO0 = __hfma2(uh2(w.w), uh2(H.y), hGO0);
                hIF1 = __hfma2(uh2(w.x), uh2(H.z), hIF1);
                hGO1 = __hfma2(uh2(w.y), uh2(H.z), hGO1);
                hIF1 = __hfma2(uh2(w.z), uh2(H.w), hIF1);
                hGO1 = __hfma2(uh2(w.w), uh2(H.w), hGO1);
                if ((j2 & 7) == 7) {
                    float2 a, b;
                    a = __half22float2(hIF0); b = __half22float2(hGO0);
                    fIF0.x += a.x; fIF0.y += a.y; fGO0.x += b.x; fGO0.y += b.y;
                    a = __half22float2(hIF1); b = __half22float2(hGO1);
                    fIF1.x += a.x; fIF1.y += a.y; fGO1.x += b.x; fGO1.y += b.y;
                    hIF0 = __float2half2_rn(0.f); hGO0 = hIF0; hIF1 = hIF0; hGO1 = hIF0;
                }
            }
            #pragma unroll 8
            for (; j2 < 128; j2++) {
                uint4 w = g_WhhH[(j2 << 8) + k];
                uint4 H = L.shD[j2];
                hIF0 = __hfma2(uh2(w.x), uh2(H.x), hIF0);
                hGO0 = __hfma2(uh2(w.y), uh2(H.x), hGO0);
                hIF0 = __hfma2(uh2(w.z), uh2(H.y), hIF0);
                hGO0 = __hfma2(uh2(w.w), uh2(H.y), hGO0);
                hIF1 = __hfma2(uh2(w.x), uh2(H.z), hIF1);
                hGO1 = __hfma2(uh2(w.y), uh2(H.z), hGO1);
                hIF1 = __hfma2(uh2(w.z), uh2(H.w), hIF1);
                hGO1 = __hfma2(uh2(w.w), uh2(H.w), hGO1);
                if ((j2 & 7) == 7) {
                    float2 a, b;
                    a = __half22float2(hIF0); b = __half22float2(hGO0);
                    fIF0.x += a.x; fIF0.y += a.y; fGO0.x += b.x; fGO0.y += b.y;
                    a = __half22float2(hIF1); b = __half22float2(hGO1);
                    fIF1.x += a.x; fIF1.y += a.y; fGO1.x += b.x; fGO1.y += b.y;
                    hIF0 = __float2half2_rn(0.f); hGO0 = hIF0; hIF1 = hIF0; hGO1 = hIF0;
                }
            }
            barn(idL, 512);   // join: y ready
            // ==== combine + state update =====================================
            {
                const float4 b4 = g_bih4[k], wi4 = g_wih4[k];
                float hnv[2], cnv[2];
                #pragma unroll
                for (int g = 0; g < 2; g++) {
                    float2 aIF = g ? fIF1 : fIF0;
                    float2 aGO = g ? fGO1 : fGO0;
                    float y = L.sy[g];
                    float gi = aIF.x + b4.x + wi4.x * y;
                    float gf = aIF.y + b4.y + wi4.y * y;
                    float gg = aGO.x + b4.z + wi4.z * y;
                    float go = aGO.y + b4.w + wi4.w * y;
                    float cold = L.shc[g][256 + k];
                    float cn = sigm(gf) * cold + sigm(gi) * tanh_acc(gg);
                    float hn = sigm(go) * tanh_acc(cn);
                    L.shc[g][256 + k] = cn;
                    L.shc[g][k] = hn;
                    hnv[g] = hn; cnv[g] = cn;
                }
                #pragma unroll
                for (int g = 0; g < 2; g++) {
                    float hnb = __shfl_down_sync(0xffffffffu, hnv[g], 1);
                    float cnb = __shfl_down_sync(0xffffffffu, cnv[g], 1);
                    ((unsigned*)&L.shD[k >> 1])[g * 2 + (k & 1)] =
                        h2u(__floats2half2_rn(hnv[g], hnv[g]));
                    if (!(k & 1)) {
                        const int slot = g * 2 + ((k >> 1) & 1);
                        L.sHA[k >> 2][slot]        = h2u(__floats2half2_rn(hnv[g], hnb));
                        L.sHA[64 + (k >> 2)][slot] = h2u(__floats2half2_rn(cnv[g], cnb));
                    }
                }
            }
            barn(idL, 512);   // state ready for next step
        }
    }
    // ==== epilogue ===========================================================
    __syncthreads();   // lanes may now reuse weight-cache smem
    {
        const int g = lt >> 8, r = lt & 255, q = r & 63, th = (r >> 6) & 3;
        const uint2* ev = (const uint2*)g_encH + ((size_t)(g0row + g) * TM1) * 64 + q;
        ull acc01 = 0ull, acc23 = 0ull;
        const int t0 = th << 5, t1 = (th == 3) ? TM1 : (t0 + 32);
        for (int t = t0; t < t1; t++) {
            float a = L.sattn[g][t];
            uint2 v = ev[(size_t)t << 6];
            float2 v01 = __half22float2(uh2(v.x)), v23 = __half22float2(uh2(v.y));
            ull A = pk2(a, a);
            fma2(acc01, A, pk2(v01.x, v01.y));
            fma2(acc23, A, pk2(v23.x, v23.y));
        }
        float2 a01 = up2(acc01), a23 = up2(acc23);
        float4* epi = (float4*)s.sWh + l * 512;
        epi[((g << 2) | th) * 64 + q] = make_float4(a01.x, a01.y, a23.x, a23.y);
    }
    barn(idL, 512);
    if (lt < 128) {
        const int g = lt >> 6, q = lt & 63;
        const float4* epi = (const float4*)s.sWh + l * 512 + (g << 2) * 64;
        float4 a = epi[q], b = epi[64 + q], c = epi[128 + q], d = epi[192 + q];
        ((float4*)L.sctx[g])[q] = make_float4(a.x + b.x + c.x + d.x,
                                              a.y + b.y + c.y + d.y,
                                              a.z + b.z + c.z + d.z,
                                              a.w + b.w + c.w + d.w);
    }
    barn(idL, 512);
    #pragma unroll
    for (int g = 0; g < 2; g++) {
        float v = (lt < 256)
                    ? (Wfcf[k] * L.shc[g][k] + Wfcf[256 + k] * L.sctx[g][k]) : 0.f;
        #pragma unroll
        for (int o = 16; o; o >>= 1) v += __shfl_down_sync(0xffffffffu, v, o);
        if (lane32 == 0) L.sred[g][lwarp] = v;
    }
    barn(idL, 512);
    if (lwarp == 0) {
        float r0 = (lane32 < 16) ? L.sred[0][lane32] : 0.f;
        float r1 = (lane32 < 16) ? L.sred[1][lane32] : 0.f;
        #pragma unroll
        for (int o = 8; o; o >>= 1) {
            r0 += __shfl_down_sync(0xffffffffu, r0, o);
            r1 += __shfl_down_sync(0xffffffffu, r1, o);
        }
        if (lane32 == 0) {
            out[g0row] = bfcf[0] + r0;
            out[g0row + 1] = bfcf[0] + r1;
        }
    }
}

// ---------------- launch -----------------------------------------------------
extern "C" void kernel_launch(void* const* d_in, const int* in_sizes, int n_in,
                              void* d_out, int out_size) {
    const float* enc  = (const float*)d_in[0];
    const float* yh   = (const float*)d_in[1];
    const float* W1   = (const float*)d_in[2];
    const float* b1   = (const float*)d_in[3];
    const float* W2   = (const float*)d_in[4];
    // d_in[5] = b_attn2: softmax-invariant, unused
    const float* Wih  = (const float*)d_in[6];
    const float* Whh  = (const float*)d_in[7];
    const float* bih  = (const float*)d_in[8];
    const float* bhh  = (const float*)d_in[9];
    const float* Wfc  = (const float*)d_in[10];
    const float* bfc  = (const float*)d_in[11];
    const float* Wfcf = (const float*)d_in[12];
    const float* bfcf = (const float*)d_in[13];
    float* out = (float*)d_out;

    static bool attr_done = false;
    if (!attr_done) {
        cudaFuncSetAttribute(decoder_kernel,
                             cudaFuncAttributeMaxDynamicSharedMemorySize, sizeof(SmemT));
        attr_done = true;
    }
    prep_kernel<<<256, 256>>>(W1, Whh, bih, bhh, Wih, enc);
    p_kernel<<<128, 256>>>(enc, Wfc);
    e_gemm<<<dim3(1016, 4), 256>>>(enc, b1);
    decoder_kernel<<<NCTA, 1024, sizeof(SmemT)>>>(yh, W2, bfc, Wfc + 256,
                                                  Wfcf, bfcf, out);
}